// round 13
// baseline (speedup 1.0000x reference)
#include <cuda_runtime.h>
#include <cuda_fp16.h>
#include <cstdint>

// Problem constants
#define DIMN    4096
#define S_LEN   2048
#define BATCH   2
#define HQ      32
#define HKV     8
#define NREP    4
#define HD      128
#define MROWS   (BATCH * S_LEN)   // 4096
#define KVDIM   (HKV * HD)        // 1024

// ---------------------------------------------------------------------------
// Scratch (__device__ globals)
// ---------------------------------------------------------------------------
__device__ __half g_xh[(size_t)MROWS * DIMN];
__device__ __half g_xl[(size_t)MROWS * DIMN];
__device__ __half g_qh[(size_t)MROWS * DIMN];
__device__ __half g_kh[(size_t)MROWS * KVDIM];
__device__ __half g_kl[(size_t)MROWS * KVDIM];
__device__ __half g_vh[(size_t)MROWS * KVDIM];
__device__ __half g_ah[(size_t)MROWS * DIMN];
__device__ __half g_wqT[(size_t)DIMN * DIMN];
__device__ __half g_woT[(size_t)DIMN * DIMN];
__device__ __half g_wkT[(size_t)KVDIM * DIMN];
__device__ __half g_wvT[(size_t)KVDIM * DIMN];

// ---------------------------------------------------------------------------
// PTX helpers
// ---------------------------------------------------------------------------
__device__ __forceinline__ uint32_t smem_u32(const void* p) {
    return (uint32_t)__cvta_generic_to_shared(p);
}
__device__ __forceinline__ void ldsm4(uint32_t* r, uint32_t addr) {
    asm volatile("ldmatrix.sync.aligned.m8n8.x4.shared.b16 {%0,%1,%2,%3}, [%4];"
                 : "=r"(r[0]), "=r"(r[1]), "=r"(r[2]), "=r"(r[3]) : "r"(addr));
}
__device__ __forceinline__ void ldsm4t(uint32_t* r, uint32_t addr) {
    asm volatile("ldmatrix.sync.aligned.m8n8.x4.trans.shared.b16 {%0,%1,%2,%3}, [%4];"
                 : "=r"(r[0]), "=r"(r[1]), "=r"(r[2]), "=r"(r[3]) : "r"(addr));
}
__device__ __forceinline__ void mma_f16(float* d, const uint32_t* a,
                                        const uint32_t b0, const uint32_t b1) {
    asm volatile(
        "mma.sync.aligned.m16n8k16.row.col.f32.f16.f16.f32 "
        "{%0,%1,%2,%3}, {%4,%5,%6,%7}, {%8,%9}, {%0,%1,%2,%3};"
        : "+f"(d[0]), "+f"(d[1]), "+f"(d[2]), "+f"(d[3])
        : "r"(a[0]), "r"(a[1]), "r"(a[2]), "r"(a[3]), "r"(b0), "r"(b1));
}
__device__ __forceinline__ uint32_t pack_h2(float a, float b) {
    __half2 t = __floats2half2_rn(a, b);
    return *(uint32_t*)&t;
}
__device__ __forceinline__ float h_res(float v) {
    return v - __half2float(__float2half_rn(v));
}

// ---------------------------------------------------------------------------
// GEMM common: K-chunk 64.
// 1-term: 3-stage ring, 1 sync/chunk. 2-term: 2-stage, 2 syncs/chunk.
// Both fit the same 110592-B budget -> 2 CTAs/SM.
// ---------------------------------------------------------------------------
constexpr int CK     = 64;
constexpr int PADW   = 72;
constexpr int PLANE  = 128 * PADW * 2;        // 18432 B
constexpr int GEMM_SMEM = 6 * PLANE;          // 110592

__device__ __forceinline__ void prefetch_rt(
    const __half* Ah, const __half* Al, const __half* Bh, int nterms,
    int K, int mtile, int ntile, int k0, uint32_t tbase, int tid)
{
    const int tot = (nterms + 1) * 1024;
    for (int u = tid; u < tot; u += 256) {
        int plane = u >> 10;
        int r = (u >> 3) & 127;
        int seg = u & 7;
        const __half* src;
        if (plane == 0)                     src = Ah + (size_t)(mtile + r) * K + k0 + seg * 8;
        else if (nterms == 2 && plane == 1) src = Al + (size_t)(mtile + r) * K + k0 + seg * 8;
        else                                src = Bh + (size_t)(ntile + r) * K + k0 + seg * 8;
        uint32_t dst = tbase + plane * PLANE + r * (PADW * 2) + seg * 16;
        asm volatile("cp.async.cg.shared.global [%0], [%1], 16;"
                     :: "r"(dst), "l"(src) : "memory");
    }
}

// ---------------------------------------------------------------------------
// Merged Q|K|V projection GEMM. grid.x = 48 column tiles:
//   [0,32): q (1-term), [32,40): k (2-term, pair out), [40,48): v (1-term)
// ---------------------------------------------------------------------------
__global__ __launch_bounds__(256, 2) void gemm_qkv(
    const __half* __restrict__ xh, const __half* __restrict__ xl,
    const __half* __restrict__ wqT, const __half* __restrict__ wkT,
    const __half* __restrict__ wvT,
    __half* __restrict__ qh, __half* __restrict__ kh,
    __half* __restrict__ kl, __half* __restrict__ vh)
{
    extern __shared__ char smem[];
    const uint32_t sbase = smem_u32(smem);

    const int tid = threadIdx.x;
    const int wid = tid >> 5, lane = tid & 31;
    const int wm = wid >> 2;
    const int wn = wid & 3;
    const int mtile = blockIdx.y * 128;
    const int nx = blockIdx.x;
    const int K = DIMN;
    const int nch = K / CK;

    const __half* B;
    __half *Oh, *Ol;
    int ntile, Nout, nterms;
    if (nx < 32)      { B = wqT; Oh = qh; Ol = nullptr; ntile = nx * 128;        Nout = DIMN;  nterms = 1; }
    else if (nx < 40) { B = wkT; Oh = kh; Ol = kl;      ntile = (nx - 32) * 128; Nout = KVDIM; nterms = 2; }
    else              { B = wvT; Oh = vh; Ol = nullptr; ntile = (nx - 40) * 128; Nout = KVDIM; nterms = 1; }

    float acc[4][4][4];
    #pragma unroll
    for (int mi = 0; mi < 4; mi++)
        #pragma unroll
        for (int ni = 0; ni < 4; ni++)
            #pragma unroll
            for (int e = 0; e < 4; e++) acc[mi][ni][e] = 0.f;

    const int a_row_in16 = (lane & 7) + ((lane >> 3) & 1) * 8;
    const int a_colb     = (lane >> 4) * 16;
    const int b_row_in16 = (lane & 7) + ((lane >> 4) & 1) * 8;
    const int b_colb     = ((lane >> 3) & 1) * 16;

    if (nterms == 1) {
        // ---- 3-stage ring, 1 sync per chunk ----
        const int STG = 2 * PLANE;
        prefetch_rt(xh, nullptr, B, 1, K, mtile, ntile, 0, sbase, tid);
        asm volatile("cp.async.commit_group;" ::: "memory");
        prefetch_rt(xh, nullptr, B, 1, K, mtile, ntile, CK, sbase + STG, tid);
        asm volatile("cp.async.commit_group;" ::: "memory");

        for (int i = 0; i < nch; i++) {
            const uint32_t tb = sbase + (i % 3) * STG;
            asm volatile("cp.async.wait_group 1;" ::: "memory");
            __syncthreads();
            if (i + 2 < nch)
                prefetch_rt(xh, nullptr, B, 1, K, mtile, ntile, (i + 2) * CK,
                            sbase + ((i + 2) % 3) * STG, tid);
            asm volatile("cp.async.commit_group;" ::: "memory");

            const uint32_t aH = tb, bH = tb + PLANE;
            #pragma unroll
            for (int ks = 0; ks < 4; ks++) {
                const int kb = ks * 32;
                uint32_t fB[2][4];
                #pragma unroll
                for (int ng = 0; ng < 2; ng++) {
                    int row = wn * 32 + ng * 16 + b_row_in16;
                    ldsm4(fB[ng], bH + row * (PADW * 2) + b_colb + kb);
                }
                uint32_t fA[4][4];
                #pragma unroll
                for (int mi = 0; mi < 4; mi++) {
                    int row = wm * 64 + mi * 16 + a_row_in16;
                    ldsm4(fA[mi], aH + row * (PADW * 2) + a_colb + kb);
                }
                #pragma unroll
                for (int mi = 0; mi < 4; mi++)
                    #pragma unroll
                    for (int ni = 0; ni < 4; ni++) {
                        const int ng = ni >> 1, hf = (ni & 1) * 2;
                        mma_f16(acc[mi][ni], fA[mi], fB[ng][hf], fB[ng][hf + 1]);
                    }
            }
        }
    } else {
        // ---- 2-term: 2-stage, 2 syncs per chunk (K segment only) ----
        const int STG = 3 * PLANE;
        for (int i = 0; i < 2; i++) {
            prefetch_rt(xh, xl, B, 2, K, mtile, ntile, i * CK, sbase + i * STG, tid);
            asm volatile("cp.async.commit_group;" ::: "memory");
        }
        for (int i = 0; i < nch; i++) {
            const uint32_t tb = sbase + (i & 1) * STG;
            asm volatile("cp.async.wait_group 1;" ::: "memory");
            __syncthreads();

            const uint32_t aH = tb, aL = tb + PLANE, bH = tb + 2 * PLANE;
            #pragma unroll
            for (int ks = 0; ks < 4; ks++) {
                const int kb = ks * 32;
                uint32_t fB[2][4];
                #pragma unroll
                for (int ng = 0; ng < 2; ng++) {
                    int row = wn * 32 + ng * 16 + b_row_in16;
                    ldsm4(fB[ng], bH + row * (PADW * 2) + b_colb + kb);
                }
                uint32_t fA[4][4];
                #pragma unroll
                for (int mi = 0; mi < 4; mi++) {
                    int row = wm * 64 + mi * 16 + a_row_in16;
                    ldsm4(fA[mi], aH + row * (PADW * 2) + a_colb + kb);
                }
                #pragma unroll
                for (int mi = 0; mi < 4; mi++)
                    #pragma unroll
                    for (int ni = 0; ni < 4; ni++) {
                        const int ng = ni >> 1, hf = (ni & 1) * 2;
                        mma_f16(acc[mi][ni], fA[mi], fB[ng][hf], fB[ng][hf + 1]);
                    }
                #pragma unroll
                for (int mi = 0; mi < 4; mi++) {
                    int row = wm * 64 + mi * 16 + a_row_in16;
                    ldsm4(fA[mi], aL + row * (PADW * 2) + a_colb + kb);
                }
                #pragma unroll
                for (int mi = 0; mi < 4; mi++)
                    #pragma unroll
                    for (int ni = 0; ni < 4; ni++) {
                        const int ng = ni >> 1, hf = (ni & 1) * 2;
                        mma_f16(acc[mi][ni], fA[mi], fB[ng][hf], fB[ng][hf + 1]);
                    }
            }
            __syncthreads();

            if (i + 2 < nch)
                prefetch_rt(xh, xl, B, 2, K, mtile, ntile, (i + 2) * CK,
                            sbase + (i & 1) * STG, tid);
            asm volatile("cp.async.commit_group;" ::: "memory");
        }
    }

    const int r0b = mtile + wm * 64 + (lane >> 2);
    const int c0b = ntile + wn * 32 + (lane & 3) * 2;
    #pragma unroll
    for (int mi = 0; mi < 4; mi++) {
        #pragma unroll
        for (int ni = 0; ni < 4; ni++) {
            size_t o0 = (size_t)(r0b + mi * 16) * Nout + c0b + ni * 8;
            size_t o1 = (size_t)(r0b + mi * 16 + 8) * Nout + c0b + ni * 8;
            float v0 = acc[mi][ni][0], v1 = acc[mi][ni][1];
            float v2 = acc[mi][ni][2], v3 = acc[mi][ni][3];
            *(uint32_t*)(Oh + o0) = pack_h2(v0, v1);
            *(uint32_t*)(Oh + o1) = pack_h2(v2, v3);
            if (Ol != nullptr) {
                *(uint32_t*)(Ol + o0) = pack_h2(h_res(v0), h_res(v1));
                *(uint32_t*)(Ol + o1) = pack_h2(h_res(v2), h_res(v3));
            }
        }
    }
}

// ---------------------------------------------------------------------------
// wo GEMM: 1-term, fp32 out, 3-stage ring (1 sync/chunk).
// ---------------------------------------------------------------------------
__global__ __launch_bounds__(256, 2) void gemm_wo(
    int M, int N, int K,
    const __half* __restrict__ Ah, const __half* __restrict__ Bh,
    float* __restrict__ C)
{
    constexpr int STG = 2 * PLANE;
    extern __shared__ char smem[];
    const uint32_t sbase = smem_u32(smem);

    const int tid = threadIdx.x;
    const int wid = tid >> 5, lane = tid & 31;
    const int wm = wid >> 2;
    const int wn = wid & 3;
    const int mtile = blockIdx.y * 128;
    const int ntile = blockIdx.x * 128;
    const int nch = K / CK;

    float acc[4][4][4];
    #pragma unroll
    for (int mi = 0; mi < 4; mi++)
        #pragma unroll
        for (int ni = 0; ni < 4; ni++)
            #pragma unroll
            for (int e = 0; e < 4; e++) acc[mi][ni][e] = 0.f;

    const int a_row_in16 = (lane & 7) + ((lane >> 3) & 1) * 8;
    const int a_colb     = (lane >> 4) * 16;
    const int b_row_in16 = (lane & 7) + ((lane >> 4) & 1) * 8;
    const int b_colb     = ((lane >> 3) & 1) * 16;

    prefetch_rt(Ah, nullptr, Bh, 1, K, mtile, ntile, 0, sbase, tid);
    asm volatile("cp.async.commit_group;" ::: "memory");
    prefetch_rt(Ah, nullptr, Bh, 1, K, mtile, ntile, CK, sbase + STG, tid);
    asm volatile("cp.async.commit_group;" ::: "memory");

    for (int i = 0; i < nch; i++) {
        const uint32_t tb = sbase + (i % 3) * STG;
        asm volatile("cp.async.wait_group 1;" ::: "memory");
        __syncthreads();
        if (i + 2 < nch)
            prefetch_rt(Ah, nullptr, Bh, 1, K, mtile, ntile, (i + 2) * CK,
                        sbase + ((i + 2) % 3) * STG, tid);
        asm volatile("cp.async.commit_group;" ::: "memory");

        const uint32_t aH = tb, bH = tb + PLANE;
        #pragma unroll
        for (int ks = 0; ks < 4; ks++) {
            const int kb = ks * 32;
            uint32_t fB[2][4];
            #pragma unroll
            for (int ng = 0; ng < 2; ng++) {
                int row = wn * 32 + ng * 16 + b_row_in16;
                ldsm4(fB[ng], bH + row * (PADW * 2) + b_colb + kb);
            }
            uint32_t fA[4][4];
            #pragma unroll
            for (int mi = 0; mi < 4; mi++) {
                int row = wm * 64 + mi * 16 + a_row_in16;
                ldsm4(fA[mi], aH + row * (PADW * 2) + a_colb + kb);
            }
            #pragma unroll
            for (int mi = 0; mi < 4; mi++)
                #pragma unroll
                for (int ni = 0; ni < 4; ni++) {
                    const int ng = ni >> 1, hf = (ni & 1) * 2;
                    mma_f16(acc[mi][ni], fA[mi], fB[ng][hf], fB[ng][hf + 1]);
                }
        }
    }

    const int r0b = mtile + wm * 64 + (lane >> 2);
    const int c0b = ntile + wn * 32 + (lane & 3) * 2;
    #pragma unroll
    for (int mi = 0; mi < 4; mi++) {
        #pragma unroll
        for (int ni = 0; ni < 4; ni++) {
            size_t o0 = (size_t)(r0b + mi * 16) * N + c0b + ni * 8;
            size_t o1 = (size_t)(r0b + mi * 16 + 8) * N + c0b + ni * 8;
            *(float2*)(C + o0) = make_float2(acc[mi][ni][0], acc[mi][ni][1]);
            *(float2*)(C + o1) = make_float2(acc[mi][ni][2], acc[mi][ni][3]);
        }
    }
}

// ---------------------------------------------------------------------------
// Conversions
// ---------------------------------------------------------------------------
__global__ void conv_pair(const float* __restrict__ in,
                          __half* __restrict__ hi, __half* __restrict__ lo, int n8)
{
    int i = blockIdx.x * blockDim.x + threadIdx.x;
    if (i >= n8) return;
    float4 v0 = ((const float4*)in)[2 * i];
    float4 v1 = ((const float4*)in)[2 * i + 1];
    uint4 h, l;
    h.x = pack_h2(v0.x, v0.y);  h.y = pack_h2(v0.z, v0.w);
    h.z = pack_h2(v1.x, v1.y);  h.w = pack_h2(v1.z, v1.w);
    l.x = pack_h2(h_res(v0.x), h_res(v0.y));
    l.y = pack_h2(h_res(v0.z), h_res(v0.w));
    l.z = pack_h2(h_res(v1.x), h_res(v1.y));
    l.w = pack_h2(h_res(v1.z), h_res(v1.w));
    ((uint4*)hi)[i] = h;
    ((uint4*)lo)[i] = l;
}

__global__ void convT_all(const float* __restrict__ wq, const float* __restrict__ wk,
                          const float* __restrict__ wv, const float* __restrict__ wo,
                          __half* __restrict__ wqT, __half* __restrict__ wkT,
                          __half* __restrict__ wvT, __half* __restrict__ woT)
{
    __shared__ float t[32][33];
    const int gx = blockIdx.x;
    const float* W;
    __half* Th;
    int n0, N;
    if (gx < 128)      { W = wq; Th = wqT; n0 = gx * 32;         N = DIMN; }
    else if (gx < 160) { W = wk; Th = wkT; n0 = (gx - 128) * 32; N = KVDIM; }
    else if (gx < 192) { W = wv; Th = wvT; n0 = (gx - 160) * 32; N = KVDIM; }
    else               { W = wo; Th = woT; n0 = (gx - 192) * 32; N = DIMN; }
    const int K = DIMN;
    int k0 = blockIdx.y * 32;
    int tx = threadIdx.x, ty0 = threadIdx.y;
    #pragma unroll
    for (int j = 0; j < 4; j++) {
        int ty = ty0 + 8 * j;
        t[ty][tx] = W[(size_t)(k0 + ty) * N + n0 + tx];
    }
    __syncthreads();
    #pragma unroll
    for (int j = 0; j < 4; j++) {
        int ty = ty0 + 8 * j;
        Th[(size_t)(n0 + ty) * K + k0 + tx] = __float2half_rn(t[tx][ty]);
    }
}

// ---------------------------------------------------------------------------
// fp16 flash attention: S = q @ (Kh+Kl)^T, O = P @ V, causal GQA.
// CTA: 128 q rows, 8 warps. K tiles of 32, 3-stage ring, 1 sync/tile.
// ---------------------------------------------------------------------------
constexpr int FB_STRIDE_B = 272;
constexpr int KT = 32;
constexpr int FPLANE  = KT * FB_STRIDE_B;       // 8704
constexpr int QPLANE  = 128 * FB_STRIDE_B;      // 34816
constexpr int FATTN_SMEM = QPLANE + 9 * FPLANE;  // 113152

__global__ __launch_bounds__(256, 2) void fattn_kernel(
    const __half* __restrict__ Qh_g,
    const __half* __restrict__ Kh_g, const __half* __restrict__ Kl_g,
    const __half* __restrict__ Vh_g,
    __half* __restrict__ Oh_g)
{
    extern __shared__ char smem[];
    const uint32_t sb = smem_u32(smem);
    const uint32_t sQh = sb;
    const uint32_t kvstart = sb + QPLANE;

    const int tid = threadIdx.x, wid = tid >> 5, lane = tid & 31;
    const int bx = gridDim.x - 1 - blockIdx.x;
    const int h = blockIdx.y, b = blockIdx.z;
    const int q0 = bx * 128;
    const int kvh = h >> 2;

    const __half* qh = Qh_g + ((size_t)(b * S_LEN + q0)) * DIMN + h * HD;
    const __half* kh = Kh_g + ((size_t)(b * S_LEN)) * KVDIM + kvh * HD;
    const __half* kl = Kl_g + ((size_t)(b * S_LEN)) * KVDIM + kvh * HD;
    const __half* vh = Vh_g + ((size_t)(b * S_LEN)) * KVDIM + kvh * HD;

    auto load_kv = [&](int kt0, int s) {
        const uint32_t base = kvstart + 3 * s * FPLANE;
        #pragma unroll
        for (int u = tid; u < 1536; u += 256) {
            int plane = u / 512, r = (u >> 4) & 31, seg = u & 15;
            const __half* src;
            if (plane == 0)      src = kh;
            else if (plane == 1) src = kl;
            else                 src = vh;
            src += (size_t)(kt0 + r) * KVDIM + seg * 8;
            uint32_t dst = base + plane * FPLANE + r * FB_STRIDE_B + seg * 16;
            asm volatile("cp.async.cg.shared.global [%0], [%1], 16;"
                         :: "r"(dst), "l"(src) : "memory");
        }
    };

    // Prologue: Q + KV(0) in group 0, KV(1) in group 1
    #pragma unroll
    for (int u = tid; u < 2048; u += 256) {
        int r = (u >> 4) & 127, seg = u & 15;
        const __half* src = qh + (size_t)r * DIMN + seg * 8;
        uint32_t dst = sQh + r * FB_STRIDE_B + seg * 16;
        asm volatile("cp.async.cg.shared.global [%0], [%1], 16;"
                     :: "r"(dst), "l"(src) : "memory");
    }
    load_kv(0, 0);
    asm volatile("cp.async.commit_group;" ::: "memory");
    load_kv(KT, 1);
    asm volatile("cp.async.commit_group;" ::: "memory");

    float accO[16][4];
    #pragma unroll
    for (int t = 0; t < 16; t++)
        #pragma unroll
        for (int e = 0; e < 4; e++) accO[t][e] = 0.f;
    float m0 = -1e30f, m1 = -1e30f, l0 = 0.f, l1 = 0.f;

    const int a_r  = (lane & 7) + ((lane >> 3) & 1) * 8;
    const int a_cb = (lane >> 4) * 16;
    const int b_r  = (lane & 7) + ((lane >> 4) & 1) * 8;
    const int b_cb = ((lane >> 3) & 1) * 16;

    const float SL = 0.08838834764831845f * 1.4426950408889634f;

    const int n_tiles = 4 * bx + 4;
    for (int t = 0; t < n_tiles; t++) {
        const int kt0 = t * KT;
        const int cur = t % 3;
        // 1 sync per tile: wait for tile t, sync (slot (t+2)%3 now free), then load.
        asm volatile("cp.async.wait_group 1;" ::: "memory");
        __syncthreads();
        if (t + 2 < n_tiles) load_kv((t + 2) * KT, (t + 2) % 3);
        asm volatile("cp.async.commit_group;" ::: "memory");

        const bool active = (kt0 <= q0 + wid * 16 + 15);

        if (active) {
            const uint32_t kvb = kvstart + 3 * cur * FPLANE;
            const uint32_t sKh = kvb, sKl = kvb + FPLANE, sVh = kvb + 2 * FPLANE;

            float accS[4][4];
            #pragma unroll
            for (int ni = 0; ni < 4; ni++)
                #pragma unroll
                for (int e = 0; e < 4; e++) accS[ni][e] = 0.f;

            #pragma unroll
            for (int kk = 0; kk < 8; kk++) {
                uint32_t fQ[4];
                uint32_t aaddr = (wid * 16 + a_r) * FB_STRIDE_B + kk * 32 + a_cb;
                ldsm4(fQ, sQh + aaddr);
                #pragma unroll
                for (int ng = 0; ng < 2; ng++) {
                    uint32_t baddr = (ng * 16 + b_r) * FB_STRIDE_B + kk * 32 + b_cb;
                    uint32_t fKh[4], fKl[4];
                    ldsm4(fKh, sKh + baddr);
                    ldsm4(fKl, sKl + baddr);
                    #pragma unroll
                    for (int hf2 = 0; hf2 < 2; hf2++) {
                        const int ni = ng * 2 + hf2;
                        mma_f16(accS[ni], fQ, fKh[hf2 * 2], fKh[hf2 * 2 + 1]);
                        mma_f16(accS[ni], fQ, fKl[hf2 * 2], fKl[hf2 * 2 + 1]);
                    }
                }
            }

            #pragma unroll
            for (int ni = 0; ni < 4; ni++)
                #pragma unroll
                for (int e = 0; e < 4; e++) accS[ni][e] *= SL;

            if (t >= n_tiles - 4) {
                const int r0 = q0 + wid * 16 + (lane >> 2);
                #pragma unroll
                for (int ni = 0; ni < 4; ni++) {
                    int c = kt0 + ni * 8 + (lane & 3) * 2;
                    if (c > r0)     accS[ni][0] = -1e30f;
                    if (c + 1 > r0) accS[ni][1] = -1e30f;
                    if (c > r0 + 8)     accS[ni][2] = -1e30f;
                    if (c + 1 > r0 + 8) accS[ni][3] = -1e30f;
                }
            }

            float mx0 = -1e30f, mx1 = -1e30f;
            #pragma unroll
            for (int ni = 0; ni < 4; ni++) {
                mx0 = fmaxf(mx0, fmaxf(accS[ni][0], accS[ni][1]));
                mx1 = fmaxf(mx1, fmaxf(accS[ni][2], accS[ni][3]));
            }
            mx0 = fmaxf(mx0, __shfl_xor_sync(0xffffffffu, mx0, 1));
            mx0 = fmaxf(mx0, __shfl_xor_sync(0xffffffffu, mx0, 2));
            mx1 = fmaxf(mx1, __shfl_xor_sync(0xffffffffu, mx1, 1));
            mx1 = fmaxf(mx1, __shfl_xor_sync(0xffffffffu, mx1, 2));

            const float mn0 = fmaxf(m0, mx0), mn1 = fmaxf(m1, mx1);
            const float al0 = exp2f(m0 - mn0), al1 = exp2f(m1 - mn1);
            m0 = mn0; m1 = mn1;

            uint32_t phA[4], phB[4];
            float s0 = 0.f, s1 = 0.f;
            #pragma unroll
            for (int ni = 0; ni < 4; ni++) {
                float p0 = exp2f(accS[ni][0] - mn0);
                float p1 = exp2f(accS[ni][1] - mn0);
                float p2 = exp2f(accS[ni][2] - mn1);
                float p3 = exp2f(accS[ni][3] - mn1);
                s0 += p0 + p1; s1 += p2 + p3;
                phA[ni] = pack_h2(p0, p1);
                phB[ni] = pack_h2(p2, p3);
            }
            s0 += __shfl_xor_sync(0xffffffffu, s0, 1);
            s0 += __shfl_xor_sync(0xffffffffu, s0, 2);
            s1 += __shfl_xor_sync(0xffffffffu, s1, 1);
            s1 += __shfl_xor_sync(0xffffffffu, s1, 2);
            l0 = l0 * al0 + s0;
            l1 = l1 * al1 + s1;

            #pragma unroll
            for (int ti = 0; ti < 16; ti++) {
                accO[ti][0] *= al0; accO[ti][1] *= al0;
                accO[ti][2] *= al1; accO[ti][3] *= al1;
            }

            #pragma unroll
            for (int j = 0; j < 2; j++) {
                uint32_t aPh[4] = { phA[2*j], phB[2*j], phA[2*j+1], phB[2*j+1] };
                #pragma unroll
                for (int dg = 0; dg < 8; dg++) {
                    uint32_t vaddr = (j * 16 + (lane & 15)) * FB_STRIDE_B
                                   + dg * 32 + (lane >> 4) * 16;
                    uint32_t fVh[4];
                    ldsm4t(fVh, sVh + vaddr);
                    mma_f16(accO[dg * 2],     aPh, fVh[0], fVh[1]);
                    mma_f16(accO[dg * 2 + 1], aPh, fVh[2], fVh[3]);
                }
            }
        }
    }

    const float inv0 = 1.0f / l0, inv1 = 1.0f / l1;
    const size_t row0 = (size_t)(b * S_LEN + q0 + wid * 16 + (lane >> 2));
    const size_t row1 = row0 + 8;
    __half* oh0 = Oh_g + row0 * DIMN + h * HD;
    __half* oh1 = Oh_g + row1 * DIMN + h * HD;
    #pragma unroll
    for (int ti = 0; ti < 16; ti++) {
        int c = ti * 8 + (lane & 3) * 2;
        *(uint32_t*)(oh0 + c) = pack_h2(accO[ti][0] * inv0, accO[ti][1] * inv0);
        *(uint32_t*)(oh1 + c) = pack_h2(accO[ti][2] * inv1, accO[ti][3] * inv1);
    }
}

// ---------------------------------------------------------------------------
// Launch
// ---------------------------------------------------------------------------
extern "C" void kernel_launch(void* const* d_in, const int* in_sizes, int n_in,
                              void* d_out, int out_size)
{
    const float* x  = (const float*)d_in[0];
    const float* wq = (const float*)d_in[1];
    const float* wk = (const float*)d_in[2];
    const float* wv = (const float*)d_in[3];
    const float* wo = (const float*)d_in[4];
    float* out = (float*)d_out;

    __half *xh, *xl, *qh, *kh, *kl, *vh, *ah;
    __half *wqT, *wkT, *wvT, *woT;
    cudaGetSymbolAddress((void**)&xh, g_xh);   cudaGetSymbolAddress((void**)&xl, g_xl);
    cudaGetSymbolAddress((void**)&qh, g_qh);
    cudaGetSymbolAddress((void**)&kh, g_kh);   cudaGetSymbolAddress((void**)&kl, g_kl);
    cudaGetSymbolAddress((void**)&vh, g_vh);
    cudaGetSymbolAddress((void**)&ah, g_ah);
    cudaGetSymbolAddress((void**)&wqT, g_wqT); cudaGetSymbolAddress((void**)&wkT, g_wkT);
    cudaGetSymbolAddress((void**)&wvT, g_wvT); cudaGetSymbolAddress((void**)&woT, g_woT);

    cudaFuncSetAttribute(gemm_qkv,
                         cudaFuncAttributeMaxDynamicSharedMemorySize, GEMM_SMEM);
    cudaFuncSetAttribute(gemm_wo,
                         cudaFuncAttributeMaxDynamicSharedMemorySize, GEMM_SMEM);
    cudaFuncSetAttribute(fattn_kernel,
                         cudaFuncAttributeMaxDynamicSharedMemorySize, FATTN_SMEM);

    int n8x = MROWS * DIMN / 8;
    conv_pair<<<(n8x + 255) / 256, 256>>>(x, xh, xl, n8x);
    convT_all<<<dim3(320, DIMN / 32), dim3(32, 8)>>>(
        wq, wk, wv, wo, wqT, wkT, wvT, woT);

    gemm_qkv<<<dim3(48, MROWS / 128), 256, GEMM_SMEM>>>(
        xh, xl, wqT, wkT, wvT, qh, kh, kl, vh);

    fattn_kernel<<<dim3(S_LEN / 128, HQ, BATCH), 256, FATTN_SMEM>>>(
        qh, kh, kl, vh, ah);

    gemm_wo<<<dim3(DIMN / 128, MROWS / 128), 256, GEMM_SMEM>>>(
        MROWS, DIMN, DIMN, ah, woT, out);
}

// round 14
// speedup vs baseline: 1.0029x; 1.0029x over previous
#include <cuda_runtime.h>
#include <cuda_fp16.h>
#include <cstdint>

// Problem constants
#define DIMN    4096
#define S_LEN   2048
#define BATCH   2
#define HQ      32
#define HKV     8
#define NREP    4
#define HD      128
#define MROWS   (BATCH * S_LEN)   // 4096
#define KVDIM   (HKV * HD)        // 1024

// ---------------------------------------------------------------------------
// Scratch (__device__ globals)
// ---------------------------------------------------------------------------
__device__ __half g_xh[(size_t)MROWS * DIMN];
__device__ __half g_xl[(size_t)MROWS * DIMN];
__device__ __half g_qh[(size_t)MROWS * DIMN];
__device__ __half g_kh[(size_t)MROWS * KVDIM];
__device__ __half g_kl[(size_t)MROWS * KVDIM];
__device__ __half g_vh[(size_t)MROWS * KVDIM];
__device__ __half g_ah[(size_t)MROWS * DIMN];
__device__ __half g_wqT[(size_t)DIMN * DIMN];
__device__ __half g_woT[(size_t)DIMN * DIMN];
__device__ __half g_wkT[(size_t)KVDIM * DIMN];
__device__ __half g_wvT[(size_t)KVDIM * DIMN];

// ---------------------------------------------------------------------------
// PTX helpers
// ---------------------------------------------------------------------------
__device__ __forceinline__ uint32_t smem_u32(const void* p) {
    return (uint32_t)__cvta_generic_to_shared(p);
}
__device__ __forceinline__ void ldsm4(uint32_t* r, uint32_t addr) {
    asm volatile("ldmatrix.sync.aligned.m8n8.x4.shared.b16 {%0,%1,%2,%3}, [%4];"
                 : "=r"(r[0]), "=r"(r[1]), "=r"(r[2]), "=r"(r[3]) : "r"(addr));
}
__device__ __forceinline__ void ldsm4t(uint32_t* r, uint32_t addr) {
    asm volatile("ldmatrix.sync.aligned.m8n8.x4.trans.shared.b16 {%0,%1,%2,%3}, [%4];"
                 : "=r"(r[0]), "=r"(r[1]), "=r"(r[2]), "=r"(r[3]) : "r"(addr));
}
__device__ __forceinline__ void mma_f16(float* d, const uint32_t* a,
                                        const uint32_t b0, const uint32_t b1) {
    asm volatile(
        "mma.sync.aligned.m16n8k16.row.col.f32.f16.f16.f32 "
        "{%0,%1,%2,%3}, {%4,%5,%6,%7}, {%8,%9}, {%0,%1,%2,%3};"
        : "+f"(d[0]), "+f"(d[1]), "+f"(d[2]), "+f"(d[3])
        : "r"(a[0]), "r"(a[1]), "r"(a[2]), "r"(a[3]), "r"(b0), "r"(b1));
}
__device__ __forceinline__ uint32_t pack_h2(float a, float b) {
    __half2 t = __floats2half2_rn(a, b);
    return *(uint32_t*)&t;
}
__device__ __forceinline__ float h_res(float v) {
    return v - __half2float(__float2half_rn(v));
}

// ---------------------------------------------------------------------------
// GEMM common: K-chunk 64, 2-stage pipeline (R12-proven form).
// ---------------------------------------------------------------------------
constexpr int CK     = 64;
constexpr int PADW   = 72;
constexpr int PLANE  = 128 * PADW * 2;        // 18432 B
constexpr int GNS    = 2;
constexpr int QKV_SMEM = GNS * 3 * PLANE;     // 110592
constexpr int WO_SMEM  = GNS * 2 * PLANE;     // 73728

__device__ __forceinline__ void prefetch_rt(
    const __half* Ah, const __half* Al, const __half* Bh, int nterms,
    int K, int mtile, int ntile, int k0, uint32_t tbase, int tid)
{
    const int tot = (nterms + 1) * 1024;
    for (int u = tid; u < tot; u += 256) {
        int plane = u >> 10;
        int r = (u >> 3) & 127;
        int seg = u & 7;
        const __half* src;
        if (plane == 0)                     src = Ah + (size_t)(mtile + r) * K + k0 + seg * 8;
        else if (nterms == 2 && plane == 1) src = Al + (size_t)(mtile + r) * K + k0 + seg * 8;
        else                                src = Bh + (size_t)(ntile + r) * K + k0 + seg * 8;
        uint32_t dst = tbase + plane * PLANE + r * (PADW * 2) + seg * 16;
        asm volatile("cp.async.cg.shared.global [%0], [%1], 16;"
                     :: "r"(dst), "l"(src) : "memory");
    }
}

// ---------------------------------------------------------------------------
// Merged Q|K|V projection GEMM. grid.x = 48, 2-term K CTAs scheduled FIRST:
//   [0,8): k (2-term, pair out), [8,40): q (1-term), [40,48): v (1-term)
// ---------------------------------------------------------------------------
__global__ __launch_bounds__(256, 2) void gemm_qkv(
    const __half* __restrict__ xh, const __half* __restrict__ xl,
    const __half* __restrict__ wqT, const __half* __restrict__ wkT,
    const __half* __restrict__ wvT,
    __half* __restrict__ qh, __half* __restrict__ kh,
    __half* __restrict__ kl, __half* __restrict__ vh)
{
    extern __shared__ char smem[];
    const uint32_t sbase = smem_u32(smem);

    const int tid = threadIdx.x;
    const int wid = tid >> 5, lane = tid & 31;
    const int wm = wid >> 2;
    const int wn = wid & 3;
    const int mtile = blockIdx.y * 128;
    const int nx = blockIdx.x;
    const int K = DIMN;
    const int nch = K / CK;

    const __half* B;
    __half *Oh, *Ol;
    int ntile, Nout, nterms;
    if (nx < 8)       { B = wkT; Oh = kh; Ol = kl;      ntile = nx * 128;        Nout = KVDIM; nterms = 2; }
    else if (nx < 40) { B = wqT; Oh = qh; Ol = nullptr; ntile = (nx - 8) * 128;  Nout = DIMN;  nterms = 1; }
    else              { B = wvT; Oh = vh; Ol = nullptr; ntile = (nx - 40) * 128; Nout = KVDIM; nterms = 1; }
    const int STG = (nterms + 1) * PLANE;

    float acc[4][4][4];
    #pragma unroll
    for (int mi = 0; mi < 4; mi++)
        #pragma unroll
        for (int ni = 0; ni < 4; ni++)
            #pragma unroll
            for (int e = 0; e < 4; e++) acc[mi][ni][e] = 0.f;

    const int a_row_in16 = (lane & 7) + ((lane >> 3) & 1) * 8;
    const int a_colb     = (lane >> 4) * 16;
    const int b_row_in16 = (lane & 7) + ((lane >> 4) & 1) * 8;
    const int b_colb     = ((lane >> 3) & 1) * 16;

    for (int i = 0; i < GNS; i++) {
        prefetch_rt(xh, xl, B, nterms, K, mtile, ntile, i * CK, sbase + i * STG, tid);
        asm volatile("cp.async.commit_group;" ::: "memory");
    }

    for (int i = 0; i < nch; i++) {
        const int s = i % GNS;
        const uint32_t tb = sbase + s * STG;
        asm volatile("cp.async.wait_group %0;" :: "n"(GNS - 1) : "memory");
        __syncthreads();

        const uint32_t aH = tb;
        const uint32_t aL = tb + PLANE;
        const uint32_t bH = tb + nterms * PLANE;

        #pragma unroll
        for (int ks = 0; ks < 4; ks++) {
            const int kb = ks * 32;
            uint32_t fB[2][4];
            #pragma unroll
            for (int ng = 0; ng < 2; ng++) {
                int row = wn * 32 + ng * 16 + b_row_in16;
                ldsm4(fB[ng], bH + row * (PADW * 2) + b_colb + kb);
            }
            uint32_t fA[4][4];
            #pragma unroll
            for (int mi = 0; mi < 4; mi++) {
                int row = wm * 64 + mi * 16 + a_row_in16;
                ldsm4(fA[mi], aH + row * (PADW * 2) + a_colb + kb);
            }
            #pragma unroll
            for (int mi = 0; mi < 4; mi++)
                #pragma unroll
                for (int ni = 0; ni < 4; ni++) {
                    const int ng = ni >> 1, hf = (ni & 1) * 2;
                    mma_f16(acc[mi][ni], fA[mi], fB[ng][hf], fB[ng][hf + 1]);
                }
            if (nterms == 2) {
                #pragma unroll
                for (int mi = 0; mi < 4; mi++) {
                    int row = wm * 64 + mi * 16 + a_row_in16;
                    ldsm4(fA[mi], aL + row * (PADW * 2) + a_colb + kb);
                }
                #pragma unroll
                for (int mi = 0; mi < 4; mi++)
                    #pragma unroll
                    for (int ni = 0; ni < 4; ni++) {
                        const int ng = ni >> 1, hf = (ni & 1) * 2;
                        mma_f16(acc[mi][ni], fA[mi], fB[ng][hf], fB[ng][hf + 1]);
                    }
            }
        }
        __syncthreads();

        if (i + GNS < nch)
            prefetch_rt(xh, xl, B, nterms, K, mtile, ntile, (i + GNS) * CK,
                        sbase + s * STG, tid);
        asm volatile("cp.async.commit_group;" ::: "memory");
    }

    const int r0b = mtile + wm * 64 + (lane >> 2);
    const int c0b = ntile + wn * 32 + (lane & 3) * 2;
    #pragma unroll
    for (int mi = 0; mi < 4; mi++) {
        #pragma unroll
        for (int ni = 0; ni < 4; ni++) {
            size_t o0 = (size_t)(r0b + mi * 16) * Nout + c0b + ni * 8;
            size_t o1 = (size_t)(r0b + mi * 16 + 8) * Nout + c0b + ni * 8;
            float v0 = acc[mi][ni][0], v1 = acc[mi][ni][1];
            float v2 = acc[mi][ni][2], v3 = acc[mi][ni][3];
            *(uint32_t*)(Oh + o0) = pack_h2(v0, v1);
            *(uint32_t*)(Oh + o1) = pack_h2(v2, v3);
            if (Ol != nullptr) {
                *(uint32_t*)(Ol + o0) = pack_h2(h_res(v0), h_res(v1));
                *(uint32_t*)(Ol + o1) = pack_h2(h_res(v2), h_res(v3));
            }
        }
    }
}

// ---------------------------------------------------------------------------
// wo GEMM: 1-term, fp32 out (R12-proven form).
// ---------------------------------------------------------------------------
__global__ __launch_bounds__(256, 2) void gemm_wo(
    int M, int N, int K,
    const __half* __restrict__ Ah, const __half* __restrict__ Bh,
    float* __restrict__ C)
{
    constexpr int STG = 2 * PLANE;
    extern __shared__ char smem[];
    const uint32_t sbase = smem_u32(smem);

    const int tid = threadIdx.x;
    const int wid = tid >> 5, lane = tid & 31;
    const int wm = wid >> 2;
    const int wn = wid & 3;
    const int mtile = blockIdx.y * 128;
    const int ntile = blockIdx.x * 128;
    const int nch = K / CK;

    float acc[4][4][4];
    #pragma unroll
    for (int mi = 0; mi < 4; mi++)
        #pragma unroll
        for (int ni = 0; ni < 4; ni++)
            #pragma unroll
            for (int e = 0; e < 4; e++) acc[mi][ni][e] = 0.f;

    const int a_row_in16 = (lane & 7) + ((lane >> 3) & 1) * 8;
    const int a_colb     = (lane >> 4) * 16;
    const int b_row_in16 = (lane & 7) + ((lane >> 4) & 1) * 8;
    const int b_colb     = ((lane >> 3) & 1) * 16;

    for (int i = 0; i < GNS; i++) {
        prefetch_rt(Ah, nullptr, Bh, 1, K, mtile, ntile, i * CK, sbase + i * STG, tid);
        asm volatile("cp.async.commit_group;" ::: "memory");
    }

    for (int i = 0; i < nch; i++) {
        const int s = i % GNS;
        const uint32_t tb = sbase + s * STG;
        asm volatile("cp.async.wait_group %0;" :: "n"(GNS - 1) : "memory");
        __syncthreads();

        const uint32_t aH = tb;
        const uint32_t bH = tb + PLANE;

        #pragma unroll
        for (int ks = 0; ks < 4; ks++) {
            const int kb = ks * 32;
            uint32_t fB[2][4];
            #pragma unroll
            for (int ng = 0; ng < 2; ng++) {
                int row = wn * 32 + ng * 16 + b_row_in16;
                ldsm4(fB[ng], bH + row * (PADW * 2) + b_colb + kb);
            }
            uint32_t fA[4][4];
            #pragma unroll
            for (int mi = 0; mi < 4; mi++) {
                int row = wm * 64 + mi * 16 + a_row_in16;
                ldsm4(fA[mi], aH + row * (PADW * 2) + a_colb + kb);
            }
            #pragma unroll
            for (int mi = 0; mi < 4; mi++)
                #pragma unroll
                for (int ni = 0; ni < 4; ni++) {
                    const int ng = ni >> 1, hf = (ni & 1) * 2;
                    mma_f16(acc[mi][ni], fA[mi], fB[ng][hf], fB[ng][hf + 1]);
                }
        }
        __syncthreads();

        if (i + GNS < nch)
            prefetch_rt(Ah, nullptr, Bh, 1, K, mtile, ntile, (i + GNS) * CK,
                        sbase + s * STG, tid);
        asm volatile("cp.async.commit_group;" ::: "memory");
    }

    const int r0b = mtile + wm * 64 + (lane >> 2);
    const int c0b = ntile + wn * 32 + (lane & 3) * 2;
    #pragma unroll
    for (int mi = 0; mi < 4; mi++) {
        #pragma unroll
        for (int ni = 0; ni < 4; ni++) {
            size_t o0 = (size_t)(r0b + mi * 16) * N + c0b + ni * 8;
            size_t o1 = (size_t)(r0b + mi * 16 + 8) * N + c0b + ni * 8;
            *(float2*)(C + o0) = make_float2(acc[mi][ni][0], acc[mi][ni][1]);
            *(float2*)(C + o1) = make_float2(acc[mi][ni][2], acc[mi][ni][3]);
        }
    }
}

// ---------------------------------------------------------------------------
// Conversions
// ---------------------------------------------------------------------------
__global__ void conv_pair(const float* __restrict__ in,
                          __half* __restrict__ hi, __half* __restrict__ lo, int n8)
{
    int i = blockIdx.x * blockDim.x + threadIdx.x;
    if (i >= n8) return;
    float4 v0 = ((const float4*)in)[2 * i];
    float4 v1 = ((const float4*)in)[2 * i + 1];
    uint4 h, l;
    h.x = pack_h2(v0.x, v0.y);  h.y = pack_h2(v0.z, v0.w);
    h.z = pack_h2(v1.x, v1.y);  h.w = pack_h2(v1.z, v1.w);
    l.x = pack_h2(h_res(v0.x), h_res(v0.y));
    l.y = pack_h2(h_res(v0.z), h_res(v0.w));
    l.z = pack_h2(h_res(v1.x), h_res(v1.y));
    l.w = pack_h2(h_res(v1.z), h_res(v1.w));
    ((uint4*)hi)[i] = h;
    ((uint4*)lo)[i] = l;
}

__global__ void convT_all(const float* __restrict__ wq, const float* __restrict__ wk,
                          const float* __restrict__ wv, const float* __restrict__ wo,
                          __half* __restrict__ wqT, __half* __restrict__ wkT,
                          __half* __restrict__ wvT, __half* __restrict__ woT)
{
    __shared__ float t[32][33];
    const int gx = blockIdx.x;
    const float* W;
    __half* Th;
    int n0, N;
    if (gx < 128)      { W = wq; Th = wqT; n0 = gx * 32;         N = DIMN; }
    else if (gx < 160) { W = wk; Th = wkT; n0 = (gx - 128) * 32; N = KVDIM; }
    else if (gx < 192) { W = wv; Th = wvT; n0 = (gx - 160) * 32; N = KVDIM; }
    else               { W = wo; Th = woT; n0 = (gx - 192) * 32; N = DIMN; }
    const int K = DIMN;
    int k0 = blockIdx.y * 32;
    int tx = threadIdx.x, ty0 = threadIdx.y;
    #pragma unroll
    for (int j = 0; j < 4; j++) {
        int ty = ty0 + 8 * j;
        t[ty][tx] = W[(size_t)(k0 + ty) * N + n0 + tx];
    }
    __syncthreads();
    #pragma unroll
    for (int j = 0; j < 4; j++) {
        int ty = ty0 + 8 * j;
        Th[(size_t)(n0 + ty) * K + k0 + tx] = __float2half_rn(t[tx][ty]);
    }
}

// ---------------------------------------------------------------------------
// fp16 flash attention: S = q @ (Kh+Kl)^T, O = P @ V, causal GQA.
// CTA: 128 q rows, 8 warps. K tiles of 32, 3-stage ring, 1 sync/tile.
// Rescale-skip: when no lane's running max changed, skip the accO rescale
// (bit-identical: exp2f(0)==1 and x*1.f==x).
// ---------------------------------------------------------------------------
constexpr int FB_STRIDE_B = 272;
constexpr int KT = 32;
constexpr int FPLANE  = KT * FB_STRIDE_B;       // 8704
constexpr int QPLANE  = 128 * FB_STRIDE_B;      // 34816
constexpr int FATTN_SMEM = QPLANE + 9 * FPLANE;  // 113152

__global__ __launch_bounds__(256, 2) void fattn_kernel(
    const __half* __restrict__ Qh_g,
    const __half* __restrict__ Kh_g, const __half* __restrict__ Kl_g,
    const __half* __restrict__ Vh_g,
    __half* __restrict__ Oh_g)
{
    extern __shared__ char smem[];
    const uint32_t sb = smem_u32(smem);
    const uint32_t sQh = sb;
    const uint32_t kvstart = sb + QPLANE;

    const int tid = threadIdx.x, wid = tid >> 5, lane = tid & 31;
    const int bx = gridDim.x - 1 - blockIdx.x;
    const int h = blockIdx.y, b = blockIdx.z;
    const int q0 = bx * 128;
    const int kvh = h >> 2;

    const __half* qh = Qh_g + ((size_t)(b * S_LEN + q0)) * DIMN + h * HD;
    const __half* kh = Kh_g + ((size_t)(b * S_LEN)) * KVDIM + kvh * HD;
    const __half* kl = Kl_g + ((size_t)(b * S_LEN)) * KVDIM + kvh * HD;
    const __half* vh = Vh_g + ((size_t)(b * S_LEN)) * KVDIM + kvh * HD;

    auto load_kv = [&](int kt0, int s) {
        const uint32_t base = kvstart + 3 * s * FPLANE;
        #pragma unroll
        for (int u = tid; u < 1536; u += 256) {
            int plane = u / 512, r = (u >> 4) & 31, seg = u & 15;
            const __half* src;
            if (plane == 0)      src = kh;
            else if (plane == 1) src = kl;
            else                 src = vh;
            src += (size_t)(kt0 + r) * KVDIM + seg * 8;
            uint32_t dst = base + plane * FPLANE + r * FB_STRIDE_B + seg * 16;
            asm volatile("cp.async.cg.shared.global [%0], [%1], 16;"
                         :: "r"(dst), "l"(src) : "memory");
        }
    };

    #pragma unroll
    for (int u = tid; u < 2048; u += 256) {
        int r = (u >> 4) & 127, seg = u & 15;
        const __half* src = qh + (size_t)r * DIMN + seg * 8;
        uint32_t dst = sQh + r * FB_STRIDE_B + seg * 16;
        asm volatile("cp.async.cg.shared.global [%0], [%1], 16;"
                     :: "r"(dst), "l"(src) : "memory");
    }
    load_kv(0, 0);
    asm volatile("cp.async.commit_group;" ::: "memory");
    load_kv(KT, 1);
    asm volatile("cp.async.commit_group;" ::: "memory");

    float accO[16][4];
    #pragma unroll
    for (int t = 0; t < 16; t++)
        #pragma unroll
        for (int e = 0; e < 4; e++) accO[t][e] = 0.f;
    float m0 = -1e30f, m1 = -1e30f, l0 = 0.f, l1 = 0.f;

    const int a_r  = (lane & 7) + ((lane >> 3) & 1) * 8;
    const int a_cb = (lane >> 4) * 16;
    const int b_r  = (lane & 7) + ((lane >> 4) & 1) * 8;
    const int b_cb = ((lane >> 3) & 1) * 16;

    const float SL = 0.08838834764831845f * 1.4426950408889634f;

    const int n_tiles = 4 * bx + 4;
    for (int t = 0; t < n_tiles; t++) {
        const int kt0 = t * KT;
        const int cur = t % 3;
        asm volatile("cp.async.wait_group 1;" ::: "memory");
        __syncthreads();
        if (t + 2 < n_tiles) load_kv((t + 2) * KT, (t + 2) % 3);
        asm volatile("cp.async.commit_group;" ::: "memory");

        const bool active = (kt0 <= q0 + wid * 16 + 15);

        if (active) {
            const uint32_t kvb = kvstart + 3 * cur * FPLANE;
            const uint32_t sKh = kvb, sKl = kvb + FPLANE, sVh = kvb + 2 * FPLANE;

            float accS[4][4];
            #pragma unroll
            for (int ni = 0; ni < 4; ni++)
                #pragma unroll
                for (int e = 0; e < 4; e++) accS[ni][e] = 0.f;

            #pragma unroll
            for (int kk = 0; kk < 8; kk++) {
                uint32_t fQ[4];
                uint32_t aaddr = (wid * 16 + a_r) * FB_STRIDE_B + kk * 32 + a_cb;
                ldsm4(fQ, sQh + aaddr);
                #pragma unroll
                for (int ng = 0; ng < 2; ng++) {
                    uint32_t baddr = (ng * 16 + b_r) * FB_STRIDE_B + kk * 32 + b_cb;
                    uint32_t fKh[4], fKl[4];
                    ldsm4(fKh, sKh + baddr);
                    ldsm4(fKl, sKl + baddr);
                    #pragma unroll
                    for (int hf2 = 0; hf2 < 2; hf2++) {
                        const int ni = ng * 2 + hf2;
                        mma_f16(accS[ni], fQ, fKh[hf2 * 2], fKh[hf2 * 2 + 1]);
                        mma_f16(accS[ni], fQ, fKl[hf2 * 2], fKl[hf2 * 2 + 1]);
                    }
                }
            }

            #pragma unroll
            for (int ni = 0; ni < 4; ni++)
                #pragma unroll
                for (int e = 0; e < 4; e++) accS[ni][e] *= SL;

            if (t >= n_tiles - 4) {
                const int r0 = q0 + wid * 16 + (lane >> 2);
                #pragma unroll
                for (int ni = 0; ni < 4; ni++) {
                    int c = kt0 + ni * 8 + (lane & 3) * 2;
                    if (c > r0)     accS[ni][0] = -1e30f;
                    if (c + 1 > r0) accS[ni][1] = -1e30f;
                    if (c > r0 + 8)     accS[ni][2] = -1e30f;
                    if (c + 1 > r0 + 8) accS[ni][3] = -1e30f;
                }
            }

            float mx0 = -1e30f, mx1 = -1e30f;
            #pragma unroll
            for (int ni = 0; ni < 4; ni++) {
                mx0 = fmaxf(mx0, fmaxf(accS[ni][0], accS[ni][1]));
                mx1 = fmaxf(mx1, fmaxf(accS[ni][2], accS[ni][3]));
            }
            mx0 = fmaxf(mx0, __shfl_xor_sync(0xffffffffu, mx0, 1));
            mx0 = fmaxf(mx0, __shfl_xor_sync(0xffffffffu, mx0, 2));
            mx1 = fmaxf(mx1, __shfl_xor_sync(0xffffffffu, mx1, 1));
            mx1 = fmaxf(mx1, __shfl_xor_sync(0xffffffffu, mx1, 2));

            const float mn0 = fmaxf(m0, mx0), mn1 = fmaxf(m1, mx1);
            const bool keep0 = (mn0 == m0), keep1 = (mn1 == m1);
            const float al0 = keep0 ? 1.0f : exp2f(m0 - mn0);
            const float al1 = keep1 ? 1.0f : exp2f(m1 - mn1);
            m0 = mn0; m1 = mn1;

            uint32_t phA[4], phB[4];
            float s0 = 0.f, s1 = 0.f;
            #pragma unroll
            for (int ni = 0; ni < 4; ni++) {
                float p0 = exp2f(accS[ni][0] - mn0);
                float p1 = exp2f(accS[ni][1] - mn0);
                float p2 = exp2f(accS[ni][2] - mn1);
                float p3 = exp2f(accS[ni][3] - mn1);
                s0 += p0 + p1; s1 += p2 + p3;
                phA[ni] = pack_h2(p0, p1);
                phB[ni] = pack_h2(p2, p3);
            }
            s0 += __shfl_xor_sync(0xffffffffu, s0, 1);
            s0 += __shfl_xor_sync(0xffffffffu, s0, 2);
            s1 += __shfl_xor_sync(0xffffffffu, s1, 1);
            s1 += __shfl_xor_sync(0xffffffffu, s1, 2);
            l0 = l0 * al0 + s0;
            l1 = l1 * al1 + s1;

            // Skip rescale when no lane's max advanced (al==1 exactly).
            if (!__all_sync(0xffffffffu, keep0 && keep1)) {
                #pragma unroll
                for (int ti = 0; ti < 16; ti++) {
                    accO[ti][0] *= al0; accO[ti][1] *= al0;
                    accO[ti][2] *= al1; accO[ti][3] *= al1;
                }
            }

            #pragma unroll
            for (int j = 0; j < 2; j++) {
                uint32_t aPh[4] = { phA[2*j], phB[2*j], phA[2*j+1], phB[2*j+1] };
                #pragma unroll
                for (int dg = 0; dg < 8; dg++) {
                    uint32_t vaddr = (j * 16 + (lane & 15)) * FB_STRIDE_B
                                   + dg * 32 + (lane >> 4) * 16;
                    uint32_t fVh[4];
                    ldsm4t(fVh, sVh + vaddr);
                    mma_f16(accO[dg * 2],     aPh, fVh[0], fVh[1]);
                    mma_f16(accO[dg * 2 + 1], aPh, fVh[2], fVh[3]);
                }
            }
        }
    }

    const float inv0 = 1.0f / l0, inv1 = 1.0f / l1;
    const size_t row0 = (size_t)(b * S_LEN + q0 + wid * 16 + (lane >> 2));
    const size_t row1 = row0 + 8;
    __half* oh0 = Oh_g + row0 * DIMN + h * HD;
    __half* oh1 = Oh_g + row1 * DIMN + h * HD;
    #pragma unroll
    for (int ti = 0; ti < 16; ti++) {
        int c = ti * 8 + (lane & 3) * 2;
        *(uint32_t*)(oh0 + c) = pack_h2(accO[ti][0] * inv0, accO[ti][1] * inv0);
        *(uint32_t*)(oh1 + c) = pack_h2(accO[ti][2] * inv1, accO[ti][3] * inv1);
    }
}

// ---------------------------------------------------------------------------
// Launch
// ---------------------------------------------------------------------------
extern "C" void kernel_launch(void* const* d_in, const int* in_sizes, int n_in,
                              void* d_out, int out_size)
{
    const float* x  = (const float*)d_in[0];
    const float* wq = (const float*)d_in[1];
    const float* wk = (const float*)d_in[2];
    const float* wv = (const float*)d_in[3];
    const float* wo = (const float*)d_in[4];
    float* out = (float*)d_out;

    __half *xh, *xl, *qh, *kh, *kl, *vh, *ah;
    __half *wqT, *wkT, *wvT, *woT;
    cudaGetSymbolAddress((void**)&xh, g_xh);   cudaGetSymbolAddress((void**)&xl, g_xl);
    cudaGetSymbolAddress((void**)&qh, g_qh);
    cudaGetSymbolAddress((void**)&kh, g_kh);   cudaGetSymbolAddress((void**)&kl, g_kl);
    cudaGetSymbolAddress((void**)&vh, g_vh);
    cudaGetSymbolAddress((void**)&ah, g_ah);
    cudaGetSymbolAddress((void**)&wqT, g_wqT); cudaGetSymbolAddress((void**)&wkT, g_wkT);
    cudaGetSymbolAddress((void**)&wvT, g_wvT); cudaGetSymbolAddress((void**)&woT, g_woT);

    cudaFuncSetAttribute(gemm_qkv,
                         cudaFuncAttributeMaxDynamicSharedMemorySize, QKV_SMEM);
    cudaFuncSetAttribute(gemm_wo,
                         cudaFuncAttributeMaxDynamicSharedMemorySize, WO_SMEM);
    cudaFuncSetAttribute(fattn_kernel,
                         cudaFuncAttributeMaxDynamicSharedMemorySize, FATTN_SMEM);

    int n8x = MROWS * DIMN / 8;
    conv_pair<<<(n8x + 255) / 256, 256>>>(x, xh, xl, n8x);
    convT_all<<<dim3(320, DIMN / 32), dim3(32, 8)>>>(
        wq, wk, wv, wo, wqT, wkT, wvT, woT);

    gemm_qkv<<<dim3(48, MROWS / 128), 256, QKV_SMEM>>>(
        xh, xl, wqT, wkT, wvT, qh, kh, kl, vh);

    fattn_kernel<<<dim3(S_LEN / 128, HQ, BATCH), 256, FATTN_SMEM>>>(
        qh, kh, kl, vh, ah);

    gemm_wo<<<dim3(DIMN / 128, MROWS / 128), 256, WO_SMEM>>>(
        MROWS, DIMN, DIMN, ah, woT, out);
}

// round 15
// speedup vs baseline: 1.0122x; 1.0093x over previous
#include <cuda_runtime.h>
#include <cuda_fp16.h>
#include <cstdint>

// Problem constants
#define DIMN    4096
#define S_LEN   2048
#define BATCH   2
#define HQ      32
#define HKV     8
#define NREP    4
#define HD      128
#define MROWS   (BATCH * S_LEN)   // 4096
#define KVDIM   (HKV * HD)        // 1024

// ---------------------------------------------------------------------------
// Scratch (__device__ globals)
// ---------------------------------------------------------------------------
__device__ __half g_xh[(size_t)MROWS * DIMN];
__device__ __half g_xl[(size_t)MROWS * DIMN];
__device__ __half g_qh[(size_t)MROWS * DIMN];
__device__ __half g_kh[(size_t)MROWS * KVDIM];
__device__ __half g_kl[(size_t)MROWS * KVDIM];
__device__ __half g_vh[(size_t)MROWS * KVDIM];
__device__ __half g_ah[(size_t)MROWS * DIMN];
__device__ __half g_wqT[(size_t)DIMN * DIMN];
__device__ __half g_woT[(size_t)DIMN * DIMN];
__device__ __half g_wkT[(size_t)KVDIM * DIMN];
__device__ __half g_wvT[(size_t)KVDIM * DIMN];

// ---------------------------------------------------------------------------
// PTX helpers
// ---------------------------------------------------------------------------
__device__ __forceinline__ uint32_t smem_u32(const void* p) {
    return (uint32_t)__cvta_generic_to_shared(p);
}
__device__ __forceinline__ void ldsm4(uint32_t* r, uint32_t addr) {
    asm volatile("ldmatrix.sync.aligned.m8n8.x4.shared.b16 {%0,%1,%2,%3}, [%4];"
                 : "=r"(r[0]), "=r"(r[1]), "=r"(r[2]), "=r"(r[3]) : "r"(addr));
}
__device__ __forceinline__ void ldsm4t(uint32_t* r, uint32_t addr) {
    asm volatile("ldmatrix.sync.aligned.m8n8.x4.trans.shared.b16 {%0,%1,%2,%3}, [%4];"
                 : "=r"(r[0]), "=r"(r[1]), "=r"(r[2]), "=r"(r[3]) : "r"(addr));
}
__device__ __forceinline__ void mma_f16(float* d, const uint32_t* a,
                                        const uint32_t b0, const uint32_t b1) {
    asm volatile(
        "mma.sync.aligned.m16n8k16.row.col.f32.f16.f16.f32 "
        "{%0,%1,%2,%3}, {%4,%5,%6,%7}, {%8,%9}, {%0,%1,%2,%3};"
        : "+f"(d[0]), "+f"(d[1]), "+f"(d[2]), "+f"(d[3])
        : "r"(a[0]), "r"(a[1]), "r"(a[2]), "r"(a[3]), "r"(b0), "r"(b1));
}
__device__ __forceinline__ uint32_t pack_h2(float a, float b) {
    __half2 t = __floats2half2_rn(a, b);
    return *(uint32_t*)&t;
}
__device__ __forceinline__ float h_res(float v) {
    return v - __half2float(__float2half_rn(v));
}

// ---------------------------------------------------------------------------
// GEMM common: K-chunk 64, 2-stage pipeline (R12-proven form).
// ---------------------------------------------------------------------------
constexpr int CK     = 64;
constexpr int PADW   = 72;
constexpr int PLANE  = 128 * PADW * 2;        // 18432 B
constexpr int GNS    = 2;
constexpr int QKV_SMEM = GNS * 3 * PLANE;     // 110592
constexpr int WO_SMEM  = GNS * 2 * PLANE;     // 73728

__device__ __forceinline__ void prefetch_rt(
    const __half* Ah, const __half* Al, const __half* Bh, int nterms,
    int K, int mtile, int ntile, int k0, uint32_t tbase, int tid)
{
    const int tot = (nterms + 1) * 1024;
    for (int u = tid; u < tot; u += 256) {
        int plane = u >> 10;
        int r = (u >> 3) & 127;
        int seg = u & 7;
        const __half* src;
        if (plane == 0)                     src = Ah + (size_t)(mtile + r) * K + k0 + seg * 8;
        else if (nterms == 2 && plane == 1) src = Al + (size_t)(mtile + r) * K + k0 + seg * 8;
        else                                src = Bh + (size_t)(ntile + r) * K + k0 + seg * 8;
        uint32_t dst = tbase + plane * PLANE + r * (PADW * 2) + seg * 16;
        asm volatile("cp.async.cg.shared.global [%0], [%1], 16;"
                     :: "r"(dst), "l"(src) : "memory");
    }
}

// ---------------------------------------------------------------------------
// Merged Q|K|V projection GEMM (R12 layout):
//   [0,32): q (1-term), [32,40): k (2-term, pair out), [40,48): v (1-term)
// ---------------------------------------------------------------------------
__global__ __launch_bounds__(256, 2) void gemm_qkv(
    const __half* __restrict__ xh, const __half* __restrict__ xl,
    const __half* __restrict__ wqT, const __half* __restrict__ wkT,
    const __half* __restrict__ wvT,
    __half* __restrict__ qh, __half* __restrict__ kh,
    __half* __restrict__ kl, __half* __restrict__ vh)
{
    extern __shared__ char smem[];
    const uint32_t sbase = smem_u32(smem);

    const int tid = threadIdx.x;
    const int wid = tid >> 5, lane = tid & 31;
    const int wm = wid >> 2;
    const int wn = wid & 3;
    const int mtile = blockIdx.y * 128;
    const int nx = blockIdx.x;
    const int K = DIMN;
    const int nch = K / CK;

    const __half* B;
    __half *Oh, *Ol;
    int ntile, Nout, nterms;
    if (nx < 32)      { B = wqT; Oh = qh; Ol = nullptr; ntile = nx * 128;        Nout = DIMN;  nterms = 1; }
    else if (nx < 40) { B = wkT; Oh = kh; Ol = kl;      ntile = (nx - 32) * 128; Nout = KVDIM; nterms = 2; }
    else              { B = wvT; Oh = vh; Ol = nullptr; ntile = (nx - 40) * 128; Nout = KVDIM; nterms = 1; }
    const int STG = (nterms + 1) * PLANE;

    float acc[4][4][4];
    #pragma unroll
    for (int mi = 0; mi < 4; mi++)
        #pragma unroll
        for (int ni = 0; ni < 4; ni++)
            #pragma unroll
            for (int e = 0; e < 4; e++) acc[mi][ni][e] = 0.f;

    const int a_row_in16 = (lane & 7) + ((lane >> 3) & 1) * 8;
    const int a_colb     = (lane >> 4) * 16;
    const int b_row_in16 = (lane & 7) + ((lane >> 4) & 1) * 8;
    const int b_colb     = ((lane >> 3) & 1) * 16;

    for (int i = 0; i < GNS; i++) {
        prefetch_rt(xh, xl, B, nterms, K, mtile, ntile, i * CK, sbase + i * STG, tid);
        asm volatile("cp.async.commit_group;" ::: "memory");
    }

    for (int i = 0; i < nch; i++) {
        const int s = i % GNS;
        const uint32_t tb = sbase + s * STG;
        asm volatile("cp.async.wait_group %0;" :: "n"(GNS - 1) : "memory");
        __syncthreads();

        const uint32_t aH = tb;
        const uint32_t aL = tb + PLANE;
        const uint32_t bH = tb + nterms * PLANE;

        #pragma unroll
        for (int ks = 0; ks < 4; ks++) {
            const int kb = ks * 32;
            uint32_t fB[2][4];
            #pragma unroll
            for (int ng = 0; ng < 2; ng++) {
                int row = wn * 32 + ng * 16 + b_row_in16;
                ldsm4(fB[ng], bH + row * (PADW * 2) + b_colb + kb);
            }
            uint32_t fA[4][4];
            #pragma unroll
            for (int mi = 0; mi < 4; mi++) {
                int row = wm * 64 + mi * 16 + a_row_in16;
                ldsm4(fA[mi], aH + row * (PADW * 2) + a_colb + kb);
            }
            #pragma unroll
            for (int mi = 0; mi < 4; mi++)
                #pragma unroll
                for (int ni = 0; ni < 4; ni++) {
                    const int ng = ni >> 1, hf = (ni & 1) * 2;
                    mma_f16(acc[mi][ni], fA[mi], fB[ng][hf], fB[ng][hf + 1]);
                }
            if (nterms == 2) {
                #pragma unroll
                for (int mi = 0; mi < 4; mi++) {
                    int row = wm * 64 + mi * 16 + a_row_in16;
                    ldsm4(fA[mi], aL + row * (PADW * 2) + a_colb + kb);
                }
                #pragma unroll
                for (int mi = 0; mi < 4; mi++)
                    #pragma unroll
                    for (int ni = 0; ni < 4; ni++) {
                        const int ng = ni >> 1, hf = (ni & 1) * 2;
                        mma_f16(acc[mi][ni], fA[mi], fB[ng][hf], fB[ng][hf + 1]);
                    }
            }
        }
        __syncthreads();

        if (i + GNS < nch)
            prefetch_rt(xh, xl, B, nterms, K, mtile, ntile, (i + GNS) * CK,
                        sbase + s * STG, tid);
        asm volatile("cp.async.commit_group;" ::: "memory");
    }

    const int r0b = mtile + wm * 64 + (lane >> 2);
    const int c0b = ntile + wn * 32 + (lane & 3) * 2;
    #pragma unroll
    for (int mi = 0; mi < 4; mi++) {
        #pragma unroll
        for (int ni = 0; ni < 4; ni++) {
            size_t o0 = (size_t)(r0b + mi * 16) * Nout + c0b + ni * 8;
            size_t o1 = (size_t)(r0b + mi * 16 + 8) * Nout + c0b + ni * 8;
            float v0 = acc[mi][ni][0], v1 = acc[mi][ni][1];
            float v2 = acc[mi][ni][2], v3 = acc[mi][ni][3];
            *(uint32_t*)(Oh + o0) = pack_h2(v0, v1);
            *(uint32_t*)(Oh + o1) = pack_h2(v2, v3);
            if (Ol != nullptr) {
                *(uint32_t*)(Ol + o0) = pack_h2(h_res(v0), h_res(v1));
                *(uint32_t*)(Ol + o1) = pack_h2(h_res(v2), h_res(v3));
            }
        }
    }
}

// ---------------------------------------------------------------------------
// wo GEMM: 1-term, fp32 out (R12-proven form).
// ---------------------------------------------------------------------------
__global__ __launch_bounds__(256, 2) void gemm_wo(
    int M, int N, int K,
    const __half* __restrict__ Ah, const __half* __restrict__ Bh,
    float* __restrict__ C)
{
    constexpr int STG = 2 * PLANE;
    extern __shared__ char smem[];
    const uint32_t sbase = smem_u32(smem);

    const int tid = threadIdx.x;
    const int wid = tid >> 5, lane = tid & 31;
    const int wm = wid >> 2;
    const int wn = wid & 3;
    const int mtile = blockIdx.y * 128;
    const int ntile = blockIdx.x * 128;
    const int nch = K / CK;

    float acc[4][4][4];
    #pragma unroll
    for (int mi = 0; mi < 4; mi++)
        #pragma unroll
        for (int ni = 0; ni < 4; ni++)
            #pragma unroll
            for (int e = 0; e < 4; e++) acc[mi][ni][e] = 0.f;

    const int a_row_in16 = (lane & 7) + ((lane >> 3) & 1) * 8;
    const int a_colb     = (lane >> 4) * 16;
    const int b_row_in16 = (lane & 7) + ((lane >> 4) & 1) * 8;
    const int b_colb     = ((lane >> 3) & 1) * 16;

    for (int i = 0; i < GNS; i++) {
        prefetch_rt(Ah, nullptr, Bh, 1, K, mtile, ntile, i * CK, sbase + i * STG, tid);
        asm volatile("cp.async.commit_group;" ::: "memory");
    }

    for (int i = 0; i < nch; i++) {
        const int s = i % GNS;
        const uint32_t tb = sbase + s * STG;
        asm volatile("cp.async.wait_group %0;" :: "n"(GNS - 1) : "memory");
        __syncthreads();

        const uint32_t aH = tb;
        const uint32_t bH = tb + PLANE;

        #pragma unroll
        for (int ks = 0; ks < 4; ks++) {
            const int kb = ks * 32;
            uint32_t fB[2][4];
            #pragma unroll
            for (int ng = 0; ng < 2; ng++) {
                int row = wn * 32 + ng * 16 + b_row_in16;
                ldsm4(fB[ng], bH + row * (PADW * 2) + b_colb + kb);
            }
            uint32_t fA[4][4];
            #pragma unroll
            for (int mi = 0; mi < 4; mi++) {
                int row = wm * 64 + mi * 16 + a_row_in16;
                ldsm4(fA[mi], aH + row * (PADW * 2) + a_colb + kb);
            }
            #pragma unroll
            for (int mi = 0; mi < 4; mi++)
                #pragma unroll
                for (int ni = 0; ni < 4; ni++) {
                    const int ng = ni >> 1, hf = (ni & 1) * 2;
                    mma_f16(acc[mi][ni], fA[mi], fB[ng][hf], fB[ng][hf + 1]);
                }
        }
        __syncthreads();

        if (i + GNS < nch)
            prefetch_rt(Ah, nullptr, Bh, 1, K, mtile, ntile, (i + GNS) * CK,
                        sbase + s * STG, tid);
        asm volatile("cp.async.commit_group;" ::: "memory");
    }

    const int r0b = mtile + wm * 64 + (lane >> 2);
    const int c0b = ntile + wn * 32 + (lane & 3) * 2;
    #pragma unroll
    for (int mi = 0; mi < 4; mi++) {
        #pragma unroll
        for (int ni = 0; ni < 4; ni++) {
            size_t o0 = (size_t)(r0b + mi * 16) * N + c0b + ni * 8;
            size_t o1 = (size_t)(r0b + mi * 16 + 8) * N + c0b + ni * 8;
            *(float2*)(C + o0) = make_float2(acc[mi][ni][0], acc[mi][ni][1]);
            *(float2*)(C + o1) = make_float2(acc[mi][ni][2], acc[mi][ni][3]);
        }
    }
}

// ---------------------------------------------------------------------------
// Merged conversion kernel: 256 threads/block, flat grid.
//   gx < 8192: x -> hi/lo pair (8 floats/thread)
//   else: weight transpose (wq|wk|wv|wo), t = gx-8192; ky=t/320, kx=t%320
// ---------------------------------------------------------------------------
__global__ void conv_all(
    const float* __restrict__ x,
    __half* __restrict__ xh, __half* __restrict__ xl,
    const float* __restrict__ wq, const float* __restrict__ wk,
    const float* __restrict__ wv, const float* __restrict__ wo,
    __half* __restrict__ wqT, __half* __restrict__ wkT,
    __half* __restrict__ wvT, __half* __restrict__ woT)
{
    const int gx = blockIdx.x;
    const int tid = threadIdx.x;
    if (gx < 8192) {
        int i = gx * 256 + tid;   // n8 = 2097152, exactly 8192 blocks
        float4 v0 = ((const float4*)x)[2 * i];
        float4 v1 = ((const float4*)x)[2 * i + 1];
        uint4 h, l;
        h.x = pack_h2(v0.x, v0.y);  h.y = pack_h2(v0.z, v0.w);
        h.z = pack_h2(v1.x, v1.y);  h.w = pack_h2(v1.z, v1.w);
        l.x = pack_h2(h_res(v0.x), h_res(v0.y));
        l.y = pack_h2(h_res(v0.z), h_res(v0.w));
        l.z = pack_h2(h_res(v1.x), h_res(v1.y));
        l.w = pack_h2(h_res(v1.z), h_res(v1.w));
        ((uint4*)xh)[i] = h;
        ((uint4*)xl)[i] = l;
        return;
    }
    __shared__ float t[32][33];
    const int tt = gx - 8192;
    const int ky = tt / 320;
    const int kx = tt - ky * 320;
    const float* W;
    __half* Th;
    int n0, N;
    if (kx < 128)      { W = wq; Th = wqT; n0 = kx * 32;         N = DIMN; }
    else if (kx < 160) { W = wk; Th = wkT; n0 = (kx - 128) * 32; N = KVDIM; }
    else if (kx < 192) { W = wv; Th = wvT; n0 = (kx - 160) * 32; N = KVDIM; }
    else               { W = wo; Th = woT; n0 = (kx - 192) * 32; N = DIMN; }
    const int K = DIMN;
    const int k0 = ky * 32;
    const int tx = tid & 31, ty0 = tid >> 5;
    #pragma unroll
    for (int j = 0; j < 4; j++) {
        int ty = ty0 + 8 * j;
        t[ty][tx] = W[(size_t)(k0 + ty) * N + n0 + tx];
    }
    __syncthreads();
    #pragma unroll
    for (int j = 0; j < 4; j++) {
        int ty = ty0 + 8 * j;
        Th[(size_t)(n0 + ty) * K + k0 + tx] = __float2half_rn(t[tx][ty]);
    }
}

// ---------------------------------------------------------------------------
// fp16 flash attention: S = q @ (Kh+Kl)^T, O = P @ V, causal GQA.
// CTA: 128 q rows, 8 warps. K tiles of 32, 3-stage ring (R12 form).
// Scale folded into the exponent: p = exp2(fma(accS, SL, -mn*SL)).
// ---------------------------------------------------------------------------
constexpr int FB_STRIDE_B = 272;
constexpr int KT = 32;
constexpr int FPLANE  = KT * FB_STRIDE_B;       // 8704
constexpr int QPLANE  = 128 * FB_STRIDE_B;      // 34816
constexpr int FATTN_SMEM = QPLANE + 9 * FPLANE;  // 113152

__global__ __launch_bounds__(256, 2) void fattn_kernel(
    const __half* __restrict__ Qh_g,
    const __half* __restrict__ Kh_g, const __half* __restrict__ Kl_g,
    const __half* __restrict__ Vh_g,
    __half* __restrict__ Oh_g)
{
    extern __shared__ char smem[];
    const uint32_t sb = smem_u32(smem);
    const uint32_t sQh = sb;
    const uint32_t kvstart = sb + QPLANE;

    const int tid = threadIdx.x, wid = tid >> 5, lane = tid & 31;
    const int bx = gridDim.x - 1 - blockIdx.x;
    const int h = blockIdx.y, b = blockIdx.z;
    const int q0 = bx * 128;
    const int kvh = h >> 2;

    const __half* qh = Qh_g + ((size_t)(b * S_LEN + q0)) * DIMN + h * HD;
    const __half* kh = Kh_g + ((size_t)(b * S_LEN)) * KVDIM + kvh * HD;
    const __half* kl = Kl_g + ((size_t)(b * S_LEN)) * KVDIM + kvh * HD;
    const __half* vh = Vh_g + ((size_t)(b * S_LEN)) * KVDIM + kvh * HD;

    auto load_kv = [&](int kt0, int s) {
        const uint32_t base = kvstart + 3 * s * FPLANE;
        #pragma unroll
        for (int u = tid; u < 1536; u += 256) {
            int plane = u / 512, r = (u >> 4) & 31, seg = u & 15;
            const __half* src;
            if (plane == 0)      src = kh;
            else if (plane == 1) src = kl;
            else                 src = vh;
            src += (size_t)(kt0 + r) * KVDIM + seg * 8;
            uint32_t dst = base + plane * FPLANE + r * FB_STRIDE_B + seg * 16;
            asm volatile("cp.async.cg.shared.global [%0], [%1], 16;"
                         :: "r"(dst), "l"(src) : "memory");
        }
    };

    #pragma unroll
    for (int u = tid; u < 2048; u += 256) {
        int r = (u >> 4) & 127, seg = u & 15;
        const __half* src = qh + (size_t)r * DIMN + seg * 8;
        uint32_t dst = sQh + r * FB_STRIDE_B + seg * 16;
        asm volatile("cp.async.cg.shared.global [%0], [%1], 16;"
                     :: "r"(dst), "l"(src) : "memory");
    }
    load_kv(0, 0);
    asm volatile("cp.async.commit_group;" ::: "memory");
    load_kv(KT, 1);
    asm volatile("cp.async.commit_group;" ::: "memory");

    float accO[16][4];
    #pragma unroll
    for (int t = 0; t < 16; t++)
        #pragma unroll
        for (int e = 0; e < 4; e++) accO[t][e] = 0.f;
    float m0 = -1e30f, m1 = -1e30f, l0 = 0.f, l1 = 0.f;

    const int a_r  = (lane & 7) + ((lane >> 3) & 1) * 8;
    const int a_cb = (lane >> 4) * 16;
    const int b_r  = (lane & 7) + ((lane >> 4) & 1) * 8;
    const int b_cb = ((lane >> 3) & 1) * 16;

    const float SL = 0.08838834764831845f * 1.4426950408889634f;

    const int n_tiles = 4 * bx + 4;
    for (int t = 0; t < n_tiles; t++) {
        const int kt0 = t * KT;
        const int cur = t % 3;
        if (t + 2 < n_tiles) load_kv((t + 2) * KT, (t + 2) % 3);
        asm volatile("cp.async.commit_group;" ::: "memory");
        asm volatile("cp.async.wait_group %0;" :: "n"(2) : "memory");
        __syncthreads();

        const bool active = (kt0 <= q0 + wid * 16 + 15);

        if (active) {
            const uint32_t kvb = kvstart + 3 * cur * FPLANE;
            const uint32_t sKh = kvb, sKl = kvb + FPLANE, sVh = kvb + 2 * FPLANE;

            float accS[4][4];
            #pragma unroll
            for (int ni = 0; ni < 4; ni++)
                #pragma unroll
                for (int e = 0; e < 4; e++) accS[ni][e] = 0.f;

            #pragma unroll
            for (int kk = 0; kk < 8; kk++) {
                uint32_t fQ[4];
                uint32_t aaddr = (wid * 16 + a_r) * FB_STRIDE_B + kk * 32 + a_cb;
                ldsm4(fQ, sQh + aaddr);
                #pragma unroll
                for (int ng = 0; ng < 2; ng++) {
                    uint32_t baddr = (ng * 16 + b_r) * FB_STRIDE_B + kk * 32 + b_cb;
                    uint32_t fKh[4], fKl[4];
                    ldsm4(fKh, sKh + baddr);
                    ldsm4(fKl, sKl + baddr);
                    #pragma unroll
                    for (int hf2 = 0; hf2 < 2; hf2++) {
                        const int ni = ng * 2 + hf2;
                        mma_f16(accS[ni], fQ, fKh[hf2 * 2], fKh[hf2 * 2 + 1]);
                        mma_f16(accS[ni], fQ, fKl[hf2 * 2], fKl[hf2 * 2 + 1]);
                    }
                }
            }

            // Causal mask in RAW logit domain
            if (t >= n_tiles - 4) {
                const int r0 = q0 + wid * 16 + (lane >> 2);
                #pragma unroll
                for (int ni = 0; ni < 4; ni++) {
                    int c = kt0 + ni * 8 + (lane & 3) * 2;
                    if (c > r0)     accS[ni][0] = -1e30f;
                    if (c + 1 > r0) accS[ni][1] = -1e30f;
                    if (c > r0 + 8)     accS[ni][2] = -1e30f;
                    if (c + 1 > r0 + 8) accS[ni][3] = -1e30f;
                }
            }

            // Row maxes (raw domain)
            float mx0 = -1e30f, mx1 = -1e30f;
            #pragma unroll
            for (int ni = 0; ni < 4; ni++) {
                mx0 = fmaxf(mx0, fmaxf(accS[ni][0], accS[ni][1]));
                mx1 = fmaxf(mx1, fmaxf(accS[ni][2], accS[ni][3]));
            }
            mx0 = fmaxf(mx0, __shfl_xor_sync(0xffffffffu, mx0, 1));
            mx0 = fmaxf(mx0, __shfl_xor_sync(0xffffffffu, mx0, 2));
            mx1 = fmaxf(mx1, __shfl_xor_sync(0xffffffffu, mx1, 1));
            mx1 = fmaxf(mx1, __shfl_xor_sync(0xffffffffu, mx1, 2));

            const float mn0 = fmaxf(m0, mx0), mn1 = fmaxf(m1, mx1);
            const float al0 = exp2f((m0 - mn0) * SL);
            const float al1 = exp2f((m1 - mn1) * SL);
            m0 = mn0; m1 = mn1;
            const float nm0 = -mn0 * SL, nm1 = -mn1 * SL;

            uint32_t phA[4], phB[4];
            float s0 = 0.f, s1 = 0.f;
            #pragma unroll
            for (int ni = 0; ni < 4; ni++) {
                float p0 = exp2f(fmaf(accS[ni][0], SL, nm0));
                float p1 = exp2f(fmaf(accS[ni][1], SL, nm0));
                float p2 = exp2f(fmaf(accS[ni][2], SL, nm1));
                float p3 = exp2f(fmaf(accS[ni][3], SL, nm1));
                s0 += p0 + p1; s1 += p2 + p3;
                phA[ni] = pack_h2(p0, p1);
                phB[ni] = pack_h2(p2, p3);
            }
            s0 += __shfl_xor_sync(0xffffffffu, s0, 1);
            s0 += __shfl_xor_sync(0xffffffffu, s0, 2);
            s1 += __shfl_xor_sync(0xffffffffu, s1, 1);
            s1 += __shfl_xor_sync(0xffffffffu, s1, 2);
            l0 = l0 * al0 + s0;
            l1 = l1 * al1 + s1;

            #pragma unroll
            for (int ti = 0; ti < 16; ti++) {
                accO[ti][0] *= al0; accO[ti][1] *= al0;
                accO[ti][2] *= al1; accO[ti][3] *= al1;
            }

            #pragma unroll
            for (int j = 0; j < 2; j++) {
                uint32_t aPh[4] = { phA[2*j], phB[2*j], phA[2*j+1], phB[2*j+1] };
                #pragma unroll
                for (int dg = 0; dg < 8; dg++) {
                    uint32_t vaddr = (j * 16 + (lane & 15)) * FB_STRIDE_B
                                   + dg * 32 + (lane >> 4) * 16;
                    uint32_t fVh[4];
                    ldsm4t(fVh, sVh + vaddr);
                    mma_f16(accO[dg * 2],     aPh, fVh[0], fVh[1]);
                    mma_f16(accO[dg * 2 + 1], aPh, fVh[2], fVh[3]);
                }
            }
        }
        __syncthreads();
    }

    const float inv0 = 1.0f / l0, inv1 = 1.0f / l1;
    const size_t row0 = (size_t)(b * S_LEN + q0 + wid * 16 + (lane >> 2));
    const size_t row1 = row0 + 8;
    __half* oh0 = Oh_g + row0 * DIMN + h * HD;
    __half* oh1 = Oh_g + row1 * DIMN + h * HD;
    #pragma unroll
    for (int ti = 0; ti < 16; ti++) {
        int c = ti * 8 + (lane & 3) * 2;
        *(uint32_t*)(oh0 + c) = pack_h2(accO[ti][0] * inv0, accO[ti][1] * inv0);
        *(uint32_t*)(oh1 + c) = pack_h2(accO[ti][2] * inv1, accO[ti][3] * inv1);
    }
}

// ---------------------------------------------------------------------------
// Launch
// ---------------------------------------------------------------------------
extern "C" void kernel_launch(void* const* d_in, const int* in_sizes, int n_in,
                              void* d_out, int out_size)
{
    const float* x  = (const float*)d_in[0];
    const float* wq = (const float*)d_in[1];
    const float* wk = (const float*)d_in[2];
    const float* wv = (const float*)d_in[3];
    const float* wo = (const float*)d_in[4];
    float* out = (float*)d_out;

    __half *xh, *xl, *qh, *kh, *kl, *vh, *ah;
    __half *wqT, *wkT, *wvT, *woT;
    cudaGetSymbolAddress((void**)&xh, g_xh);   cudaGetSymbolAddress((void**)&xl, g_xl);
    cudaGetSymbolAddress((void**)&qh, g_qh);
    cudaGetSymbolAddress((void**)&kh, g_kh);   cudaGetSymbolAddress((void**)&kl, g_kl);
    cudaGetSymbolAddress((void**)&vh, g_vh);
    cudaGetSymbolAddress((void**)&ah, g_ah);
    cudaGetSymbolAddress((void**)&wqT, g_wqT); cudaGetSymbolAddress((void**)&wkT, g_wkT);
    cudaGetSymbolAddress((void**)&wvT, g_wvT); cudaGetSymbolAddress((void**)&woT, g_woT);

    cudaFuncSetAttribute(gemm_qkv,
                         cudaFuncAttributeMaxDynamicSharedMemorySize, QKV_SMEM);
    cudaFuncSetAttribute(gemm_wo,
                         cudaFuncAttributeMaxDynamicSharedMemorySize, WO_SMEM);
    cudaFuncSetAttribute(fattn_kernel,
                         cudaFuncAttributeMaxDynamicSharedMemorySize, FATTN_SMEM);

    // Merged conversions: 8192 conv blocks + 320*128 transpose blocks
    conv_all<<<8192 + 320 * 128, 256>>>(
        x, xh, xl, wq, wk, wv, wo, wqT, wkT, wvT, woT);

    gemm_qkv<<<dim3(48, MROWS / 128), 256, QKV_SMEM>>>(
        xh, xl, wqT, wkT, wvT, qh, kh, kl, vh);

    fattn_kernel<<<dim3(S_LEN / 128, HQ, BATCH), 256, FATTN_SMEM>>>(
        qh, kh, kl, vh, ah);

    gemm_wo<<<dim3(DIMN / 128, MROWS / 128), 256, WO_SMEM>>>(
        MROWS, DIMN, DIMN, ah, woT, out);
}

// round 16
// speedup vs baseline: 1.0222x; 1.0099x over previous
#include <cuda_runtime.h>
#include <cuda_fp16.h>
#include <cstdint>

// Problem constants
#define DIMN    4096
#define S_LEN   2048
#define BATCH   2
#define HQ      32
#define HKV     8
#define NREP    4
#define HD      128
#define MROWS   (BATCH * S_LEN)   // 4096
#define KVDIM   (HKV * HD)        // 1024
#define NSM_CTAS 296              // 148 SMs x 2 CTAs

// ---------------------------------------------------------------------------
// Scratch (__device__ globals)
// ---------------------------------------------------------------------------
__device__ __half g_xh[(size_t)MROWS * DIMN];
__device__ __half g_xl[(size_t)MROWS * DIMN];
__device__ __half g_qh[(size_t)MROWS * DIMN];
__device__ __half g_kh[(size_t)MROWS * KVDIM];
__device__ __half g_kl[(size_t)MROWS * KVDIM];
__device__ __half g_vh[(size_t)MROWS * KVDIM];
__device__ __half g_ah[(size_t)MROWS * DIMN];
__device__ __half g_wqT[(size_t)DIMN * DIMN];
__device__ __half g_woT[(size_t)DIMN * DIMN];
__device__ __half g_wkT[(size_t)KVDIM * DIMN];
__device__ __half g_wvT[(size_t)KVDIM * DIMN];

// ---------------------------------------------------------------------------
// PTX helpers
// ---------------------------------------------------------------------------
__device__ __forceinline__ uint32_t smem_u32(const void* p) {
    return (uint32_t)__cvta_generic_to_shared(p);
}
__device__ __forceinline__ void ldsm4(uint32_t* r, uint32_t addr) {
    asm volatile("ldmatrix.sync.aligned.m8n8.x4.shared.b16 {%0,%1,%2,%3}, [%4];"
                 : "=r"(r[0]), "=r"(r[1]), "=r"(r[2]), "=r"(r[3]) : "r"(addr));
}
__device__ __forceinline__ void ldsm4t(uint32_t* r, uint32_t addr) {
    asm volatile("ldmatrix.sync.aligned.m8n8.x4.trans.shared.b16 {%0,%1,%2,%3}, [%4];"
                 : "=r"(r[0]), "=r"(r[1]), "=r"(r[2]), "=r"(r[3]) : "r"(addr));
}
__device__ __forceinline__ void mma_f16(float* d, const uint32_t* a,
                                        const uint32_t b0, const uint32_t b1) {
    asm volatile(
        "mma.sync.aligned.m16n8k16.row.col.f32.f16.f16.f32 "
        "{%0,%1,%2,%3}, {%4,%5,%6,%7}, {%8,%9}, {%0,%1,%2,%3};"
        : "+f"(d[0]), "+f"(d[1]), "+f"(d[2]), "+f"(d[3])
        : "r"(a[0]), "r"(a[1]), "r"(a[2]), "r"(a[3]), "r"(b0), "r"(b1));
}
__device__ __forceinline__ uint32_t pack_h2(float a, float b) {
    __half2 t = __floats2half2_rn(a, b);
    return *(uint32_t*)&t;
}
__device__ __forceinline__ float h_res(float v) {
    return v - __half2float(__float2half_rn(v));
}

// ---------------------------------------------------------------------------
// GEMM common: K-chunk 64, 2-stage pipeline (R12 math), persistent tiles.
// ---------------------------------------------------------------------------
constexpr int CK     = 64;
constexpr int PADW   = 72;
constexpr int PLANE  = 128 * PADW * 2;        // 18432 B
constexpr int GNS    = 2;
constexpr int QKV_SMEM = GNS * 3 * PLANE;     // 110592
constexpr int WO_SMEM  = GNS * 2 * PLANE;     // 73728

__device__ __forceinline__ void prefetch_rt(
    const __half* Ah, const __half* Al, const __half* Bh, int nterms,
    int K, int mtile, int ntile, int k0, uint32_t tbase, int tid)
{
    const int tot = (nterms + 1) * 1024;
    for (int u = tid; u < tot; u += 256) {
        int plane = u >> 10;
        int r = (u >> 3) & 127;
        int seg = u & 7;
        const __half* src;
        if (plane == 0)                     src = Ah + (size_t)(mtile + r) * K + k0 + seg * 8;
        else if (nterms == 2 && plane == 1) src = Al + (size_t)(mtile + r) * K + k0 + seg * 8;
        else                                src = Bh + (size_t)(ntile + r) * K + k0 + seg * 8;
        uint32_t dst = tbase + plane * PLANE + r * (PADW * 2) + seg * 16;
        asm volatile("cp.async.cg.shared.global [%0], [%1], 16;"
                     :: "r"(dst), "l"(src) : "memory");
    }
}

// ---------------------------------------------------------------------------
// Persistent merged Q|K|V projection GEMM. 1536 tiles over NSM_CTAS CTAs.
// Tile decode: nx = t % 48 -> [0,32): q, [32,40): k (2-term), [40,48): v
// ---------------------------------------------------------------------------
__global__ __launch_bounds__(256, 2) void gemm_qkv(
    const __half* __restrict__ xh, const __half* __restrict__ xl,
    const __half* __restrict__ wqT, const __half* __restrict__ wkT,
    const __half* __restrict__ wvT,
    __half* __restrict__ qh, __half* __restrict__ kh,
    __half* __restrict__ kl, __half* __restrict__ vh)
{
    extern __shared__ char smem[];
    const uint32_t sbase = smem_u32(smem);

    const int tid = threadIdx.x;
    const int wid = tid >> 5, lane = tid & 31;
    const int wm = wid >> 2;
    const int wn = wid & 3;
    const int K = DIMN;
    const int nch = K / CK;

    const int a_row_in16 = (lane & 7) + ((lane >> 3) & 1) * 8;
    const int a_colb     = (lane >> 4) * 16;
    const int b_row_in16 = (lane & 7) + ((lane >> 4) & 1) * 8;
    const int b_colb     = ((lane >> 3) & 1) * 16;

    for (int tix = blockIdx.x; tix < 48 * (MROWS / 128); tix += gridDim.x) {
        const int nx = tix % 48;
        const int mtile = (tix / 48) * 128;

        const __half* B;
        __half *Oh, *Ol;
        int ntile, Nout, nterms;
        if (nx < 32)      { B = wqT; Oh = qh; Ol = nullptr; ntile = nx * 128;        Nout = DIMN;  nterms = 1; }
        else if (nx < 40) { B = wkT; Oh = kh; Ol = kl;      ntile = (nx - 32) * 128; Nout = KVDIM; nterms = 2; }
        else              { B = wvT; Oh = vh; Ol = nullptr; ntile = (nx - 40) * 128; Nout = KVDIM; nterms = 1; }
        const int STG = (nterms + 1) * PLANE;

        float acc[4][4][4];
        #pragma unroll
        for (int mi = 0; mi < 4; mi++)
            #pragma unroll
            for (int ni = 0; ni < 4; ni++)
                #pragma unroll
                for (int e = 0; e < 4; e++) acc[mi][ni][e] = 0.f;

        for (int i = 0; i < GNS; i++) {
            prefetch_rt(xh, xl, B, nterms, K, mtile, ntile, i * CK, sbase + i * STG, tid);
            asm volatile("cp.async.commit_group;" ::: "memory");
        }

        for (int i = 0; i < nch; i++) {
            const int s = i % GNS;
            const uint32_t tb = sbase + s * STG;
            asm volatile("cp.async.wait_group %0;" :: "n"(GNS - 1) : "memory");
            __syncthreads();

            const uint32_t aH = tb;
            const uint32_t aL = tb + PLANE;
            const uint32_t bH = tb + nterms * PLANE;

            #pragma unroll
            for (int ks = 0; ks < 4; ks++) {
                const int kb = ks * 32;
                uint32_t fB[2][4];
                #pragma unroll
                for (int ng = 0; ng < 2; ng++) {
                    int row = wn * 32 + ng * 16 + b_row_in16;
                    ldsm4(fB[ng], bH + row * (PADW * 2) + b_colb + kb);
                }
                uint32_t fA[4][4];
                #pragma unroll
                for (int mi = 0; mi < 4; mi++) {
                    int row = wm * 64 + mi * 16 + a_row_in16;
                    ldsm4(fA[mi], aH + row * (PADW * 2) + a_colb + kb);
                }
                #pragma unroll
                for (int mi = 0; mi < 4; mi++)
                    #pragma unroll
                    for (int ni = 0; ni < 4; ni++) {
                        const int ng = ni >> 1, hf = (ni & 1) * 2;
                        mma_f16(acc[mi][ni], fA[mi], fB[ng][hf], fB[ng][hf + 1]);
                    }
                if (nterms == 2) {
                    #pragma unroll
                    for (int mi = 0; mi < 4; mi++) {
                        int row = wm * 64 + mi * 16 + a_row_in16;
                        ldsm4(fA[mi], aL + row * (PADW * 2) + a_colb + kb);
                    }
                    #pragma unroll
                    for (int mi = 0; mi < 4; mi++)
                        #pragma unroll
                        for (int ni = 0; ni < 4; ni++) {
                            const int ng = ni >> 1, hf = (ni & 1) * 2;
                            mma_f16(acc[mi][ni], fA[mi], fB[ng][hf], fB[ng][hf + 1]);
                        }
                }
            }
            __syncthreads();

            if (i + GNS < nch)
                prefetch_rt(xh, xl, B, nterms, K, mtile, ntile, (i + GNS) * CK,
                            sbase + s * STG, tid);
            asm volatile("cp.async.commit_group;" ::: "memory");
        }

        const int r0b = mtile + wm * 64 + (lane >> 2);
        const int c0b = ntile + wn * 32 + (lane & 3) * 2;
        #pragma unroll
        for (int mi = 0; mi < 4; mi++) {
            #pragma unroll
            for (int ni = 0; ni < 4; ni++) {
                size_t o0 = (size_t)(r0b + mi * 16) * Nout + c0b + ni * 8;
                size_t o1 = (size_t)(r0b + mi * 16 + 8) * Nout + c0b + ni * 8;
                float v0 = acc[mi][ni][0], v1 = acc[mi][ni][1];
                float v2 = acc[mi][ni][2], v3 = acc[mi][ni][3];
                *(uint32_t*)(Oh + o0) = pack_h2(v0, v1);
                *(uint32_t*)(Oh + o1) = pack_h2(v2, v3);
                if (Ol != nullptr) {
                    *(uint32_t*)(Ol + o0) = pack_h2(h_res(v0), h_res(v1));
                    *(uint32_t*)(Ol + o1) = pack_h2(h_res(v2), h_res(v3));
                }
            }
        }
    }
}

// ---------------------------------------------------------------------------
// Persistent wo GEMM: 1-term, fp32 out. 1024 tiles over NSM_CTAS CTAs.
// ---------------------------------------------------------------------------
__global__ __launch_bounds__(256, 2) void gemm_wo(
    int M, int N, int K,
    const __half* __restrict__ Ah, const __half* __restrict__ Bh,
    float* __restrict__ C)
{
    constexpr int STG = 2 * PLANE;
    extern __shared__ char smem[];
    const uint32_t sbase = smem_u32(smem);

    const int tid = threadIdx.x;
    const int wid = tid >> 5, lane = tid & 31;
    const int wm = wid >> 2;
    const int wn = wid & 3;
    const int nch = K / CK;
    const int ntiles_n = N / 128;
    const int ntiles = (M / 128) * ntiles_n;

    const int a_row_in16 = (lane & 7) + ((lane >> 3) & 1) * 8;
    const int a_colb     = (lane >> 4) * 16;
    const int b_row_in16 = (lane & 7) + ((lane >> 4) & 1) * 8;
    const int b_colb     = ((lane >> 3) & 1) * 16;

    for (int tix = blockIdx.x; tix < ntiles; tix += gridDim.x) {
        const int mtile = (tix / ntiles_n) * 128;
        const int ntile = (tix % ntiles_n) * 128;

        float acc[4][4][4];
        #pragma unroll
        for (int mi = 0; mi < 4; mi++)
            #pragma unroll
            for (int ni = 0; ni < 4; ni++)
                #pragma unroll
                for (int e = 0; e < 4; e++) acc[mi][ni][e] = 0.f;

        for (int i = 0; i < GNS; i++) {
            prefetch_rt(Ah, nullptr, Bh, 1, K, mtile, ntile, i * CK, sbase + i * STG, tid);
            asm volatile("cp.async.commit_group;" ::: "memory");
        }

        for (int i = 0; i < nch; i++) {
            const int s = i % GNS;
            const uint32_t tb = sbase + s * STG;
            asm volatile("cp.async.wait_group %0;" :: "n"(GNS - 1) : "memory");
            __syncthreads();

            const uint32_t aH = tb;
            const uint32_t bH = tb + PLANE;

            #pragma unroll
            for (int ks = 0; ks < 4; ks++) {
                const int kb = ks * 32;
                uint32_t fB[2][4];
                #pragma unroll
                for (int ng = 0; ng < 2; ng++) {
                    int row = wn * 32 + ng * 16 + b_row_in16;
                    ldsm4(fB[ng], bH + row * (PADW * 2) + b_colb + kb);
                }
                uint32_t fA[4][4];
                #pragma unroll
                for (int mi = 0; mi < 4; mi++) {
                    int row = wm * 64 + mi * 16 + a_row_in16;
                    ldsm4(fA[mi], aH + row * (PADW * 2) + a_colb + kb);
                }
                #pragma unroll
                for (int mi = 0; mi < 4; mi++)
                    #pragma unroll
                    for (int ni = 0; ni < 4; ni++) {
                        const int ng = ni >> 1, hf = (ni & 1) * 2;
                        mma_f16(acc[mi][ni], fA[mi], fB[ng][hf], fB[ng][hf + 1]);
                    }
            }
            __syncthreads();

            if (i + GNS < nch)
                prefetch_rt(Ah, nullptr, Bh, 1, K, mtile, ntile, (i + GNS) * CK,
                            sbase + s * STG, tid);
            asm volatile("cp.async.commit_group;" ::: "memory");
        }

        const int r0b = mtile + wm * 64 + (lane >> 2);
        const int c0b = ntile + wn * 32 + (lane & 3) * 2;
        #pragma unroll
        for (int mi = 0; mi < 4; mi++) {
            #pragma unroll
            for (int ni = 0; ni < 4; ni++) {
                size_t o0 = (size_t)(r0b + mi * 16) * N + c0b + ni * 8;
                size_t o1 = (size_t)(r0b + mi * 16 + 8) * N + c0b + ni * 8;
                *(float2*)(C + o0) = make_float2(acc[mi][ni][0], acc[mi][ni][1]);
                *(float2*)(C + o1) = make_float2(acc[mi][ni][2], acc[mi][ni][3]);
            }
        }
    }
}

// ---------------------------------------------------------------------------
// Merged conversion kernel (R15 form).
// ---------------------------------------------------------------------------
__global__ void conv_all(
    const float* __restrict__ x,
    __half* __restrict__ xh, __half* __restrict__ xl,
    const float* __restrict__ wq, const float* __restrict__ wk,
    const float* __restrict__ wv, const float* __restrict__ wo,
    __half* __restrict__ wqT, __half* __restrict__ wkT,
    __half* __restrict__ wvT, __half* __restrict__ woT)
{
    const int gx = blockIdx.x;
    const int tid = threadIdx.x;
    if (gx < 8192) {
        int i = gx * 256 + tid;
        float4 v0 = ((const float4*)x)[2 * i];
        float4 v1 = ((const float4*)x)[2 * i + 1];
        uint4 h, l;
        h.x = pack_h2(v0.x, v0.y);  h.y = pack_h2(v0.z, v0.w);
        h.z = pack_h2(v1.x, v1.y);  h.w = pack_h2(v1.z, v1.w);
        l.x = pack_h2(h_res(v0.x), h_res(v0.y));
        l.y = pack_h2(h_res(v0.z), h_res(v0.w));
        l.z = pack_h2(h_res(v1.x), h_res(v1.y));
        l.w = pack_h2(h_res(v1.z), h_res(v1.w));
        ((uint4*)xh)[i] = h;
        ((uint4*)xl)[i] = l;
        return;
    }
    __shared__ float t[32][33];
    const int tt = gx - 8192;
    const int ky = tt / 320;
    const int kx = tt - ky * 320;
    const float* W;
    __half* Th;
    int n0, N;
    if (kx < 128)      { W = wq; Th = wqT; n0 = kx * 32;         N = DIMN; }
    else if (kx < 160) { W = wk; Th = wkT; n0 = (kx - 128) * 32; N = KVDIM; }
    else if (kx < 192) { W = wv; Th = wvT; n0 = (kx - 160) * 32; N = KVDIM; }
    else               { W = wo; Th = woT; n0 = (kx - 192) * 32; N = DIMN; }
    const int K = DIMN;
    const int k0 = ky * 32;
    const int tx = tid & 31, ty0 = tid >> 5;
    #pragma unroll
    for (int j = 0; j < 4; j++) {
        int ty = ty0 + 8 * j;
        t[ty][tx] = W[(size_t)(k0 + ty) * N + n0 + tx];
    }
    __syncthreads();
    #pragma unroll
    for (int j = 0; j < 4; j++) {
        int ty = ty0 + 8 * j;
        Th[(size_t)(n0 + ty) * K + k0 + tx] = __float2half_rn(t[tx][ty]);
    }
}

// ---------------------------------------------------------------------------
// fp16 flash attention (R15 form, unchanged).
// ---------------------------------------------------------------------------
constexpr int FB_STRIDE_B = 272;
constexpr int KT = 32;
constexpr int FPLANE  = KT * FB_STRIDE_B;       // 8704
constexpr int QPLANE  = 128 * FB_STRIDE_B;      // 34816
constexpr int FATTN_SMEM = QPLANE + 9 * FPLANE;  // 113152

__global__ __launch_bounds__(256, 2) void fattn_kernel(
    const __half* __restrict__ Qh_g,
    const __half* __restrict__ Kh_g, const __half* __restrict__ Kl_g,
    const __half* __restrict__ Vh_g,
    __half* __restrict__ Oh_g)
{
    extern __shared__ char smem[];
    const uint32_t sb = smem_u32(smem);
    const uint32_t sQh = sb;
    const uint32_t kvstart = sb + QPLANE;

    const int tid = threadIdx.x, wid = tid >> 5, lane = tid & 31;
    const int bx = gridDim.x - 1 - blockIdx.x;
    const int h = blockIdx.y, b = blockIdx.z;
    const int q0 = bx * 128;
    const int kvh = h >> 2;

    const __half* qh = Qh_g + ((size_t)(b * S_LEN + q0)) * DIMN + h * HD;
    const __half* kh = Kh_g + ((size_t)(b * S_LEN)) * KVDIM + kvh * HD;
    const __half* kl = Kl_g + ((size_t)(b * S_LEN)) * KVDIM + kvh * HD;
    const __half* vh = Vh_g + ((size_t)(b * S_LEN)) * KVDIM + kvh * HD;

    auto load_kv = [&](int kt0, int s) {
        const uint32_t base = kvstart + 3 * s * FPLANE;
        #pragma unroll
        for (int u = tid; u < 1536; u += 256) {
            int plane = u / 512, r = (u >> 4) & 31, seg = u & 15;
            const __half* src;
            if (plane == 0)      src = kh;
            else if (plane == 1) src = kl;
            else                 src = vh;
            src += (size_t)(kt0 + r) * KVDIM + seg * 8;
            uint32_t dst = base + plane * FPLANE + r * FB_STRIDE_B + seg * 16;
            asm volatile("cp.async.cg.shared.global [%0], [%1], 16;"
                         :: "r"(dst), "l"(src) : "memory");
        }
    };

    #pragma unroll
    for (int u = tid; u < 2048; u += 256) {
        int r = (u >> 4) & 127, seg = u & 15;
        const __half* src = qh + (size_t)r * DIMN + seg * 8;
        uint32_t dst = sQh + r * FB_STRIDE_B + seg * 16;
        asm volatile("cp.async.cg.shared.global [%0], [%1], 16;"
                     :: "r"(dst), "l"(src) : "memory");
    }
    load_kv(0, 0);
    asm volatile("cp.async.commit_group;" ::: "memory");
    load_kv(KT, 1);
    asm volatile("cp.async.commit_group;" ::: "memory");

    float accO[16][4];
    #pragma unroll
    for (int t = 0; t < 16; t++)
        #pragma unroll
        for (int e = 0; e < 4; e++) accO[t][e] = 0.f;
    float m0 = -1e30f, m1 = -1e30f, l0 = 0.f, l1 = 0.f;

    const int a_r  = (lane & 7) + ((lane >> 3) & 1) * 8;
    const int a_cb = (lane >> 4) * 16;
    const int b_r  = (lane & 7) + ((lane >> 4) & 1) * 8;
    const int b_cb = ((lane >> 3) & 1) * 16;

    const float SL = 0.08838834764831845f * 1.4426950408889634f;

    const int n_tiles = 4 * bx + 4;
    for (int t = 0; t < n_tiles; t++) {
        const int kt0 = t * KT;
        const int cur = t % 3;
        if (t + 2 < n_tiles) load_kv((t + 2) * KT, (t + 2) % 3);
        asm volatile("cp.async.commit_group;" ::: "memory");
        asm volatile("cp.async.wait_group %0;" :: "n"(2) : "memory");
        __syncthreads();

        const bool active = (kt0 <= q0 + wid * 16 + 15);

        if (active) {
            const uint32_t kvb = kvstart + 3 * cur * FPLANE;
            const uint32_t sKh = kvb, sKl = kvb + FPLANE, sVh = kvb + 2 * FPLANE;

            float accS[4][4];
            #pragma unroll
            for (int ni = 0; ni < 4; ni++)
                #pragma unroll
                for (int e = 0; e < 4; e++) accS[ni][e] = 0.f;

            #pragma unroll
            for (int kk = 0; kk < 8; kk++) {
                uint32_t fQ[4];
                uint32_t aaddr = (wid * 16 + a_r) * FB_STRIDE_B + kk * 32 + a_cb;
                ldsm4(fQ, sQh + aaddr);
                #pragma unroll
                for (int ng = 0; ng < 2; ng++) {
                    uint32_t baddr = (ng * 16 + b_r) * FB_STRIDE_B + kk * 32 + b_cb;
                    uint32_t fKh[4], fKl[4];
                    ldsm4(fKh, sKh + baddr);
                    ldsm4(fKl, sKl + baddr);
                    #pragma unroll
                    for (int hf2 = 0; hf2 < 2; hf2++) {
                        const int ni = ng * 2 + hf2;
                        mma_f16(accS[ni], fQ, fKh[hf2 * 2], fKh[hf2 * 2 + 1]);
                        mma_f16(accS[ni], fQ, fKl[hf2 * 2], fKl[hf2 * 2 + 1]);
                    }
                }
            }

            if (t >= n_tiles - 4) {
                const int r0 = q0 + wid * 16 + (lane >> 2);
                #pragma unroll
                for (int ni = 0; ni < 4; ni++) {
                    int c = kt0 + ni * 8 + (lane & 3) * 2;
                    if (c > r0)     accS[ni][0] = -1e30f;
                    if (c + 1 > r0) accS[ni][1] = -1e30f;
                    if (c > r0 + 8)     accS[ni][2] = -1e30f;
                    if (c + 1 > r0 + 8) accS[ni][3] = -1e30f;
                }
            }

            float mx0 = -1e30f, mx1 = -1e30f;
            #pragma unroll
            for (int ni = 0; ni < 4; ni++) {
                mx0 = fmaxf(mx0, fmaxf(accS[ni][0], accS[ni][1]));
                mx1 = fmaxf(mx1, fmaxf(accS[ni][2], accS[ni][3]));
            }
            mx0 = fmaxf(mx0, __shfl_xor_sync(0xffffffffu, mx0, 1));
            mx0 = fmaxf(mx0, __shfl_xor_sync(0xffffffffu, mx0, 2));
            mx1 = fmaxf(mx1, __shfl_xor_sync(0xffffffffu, mx1, 1));
            mx1 = fmaxf(mx1, __shfl_xor_sync(0xffffffffu, mx1, 2));

            const float mn0 = fmaxf(m0, mx0), mn1 = fmaxf(m1, mx1);
            const float al0 = exp2f((m0 - mn0) * SL);
            const float al1 = exp2f((m1 - mn1) * SL);
            m0 = mn0; m1 = mn1;
            const float nm0 = -mn0 * SL, nm1 = -mn1 * SL;

            uint32_t phA[4], phB[4];
            float s0 = 0.f, s1 = 0.f;
            #pragma unroll
            for (int ni = 0; ni < 4; ni++) {
                float p0 = exp2f(fmaf(accS[ni][0], SL, nm0));
                float p1 = exp2f(fmaf(accS[ni][1], SL, nm0));
                float p2 = exp2f(fmaf(accS[ni][2], SL, nm1));
                float p3 = exp2f(fmaf(accS[ni][3], SL, nm1));
                s0 += p0 + p1; s1 += p2 + p3;
                phA[ni] = pack_h2(p0, p1);
                phB[ni] = pack_h2(p2, p3);
            }
            s0 += __shfl_xor_sync(0xffffffffu, s0, 1);
            s0 += __shfl_xor_sync(0xffffffffu, s0, 2);
            s1 += __shfl_xor_sync(0xffffffffu, s1, 1);
            s1 += __shfl_xor_sync(0xffffffffu, s1, 2);
            l0 = l0 * al0 + s0;
            l1 = l1 * al1 + s1;

            #pragma unroll
            for (int ti = 0; ti < 16; ti++) {
                accO[ti][0] *= al0; accO[ti][1] *= al0;
                accO[ti][2] *= al1; accO[ti][3] *= al1;
            }

            #pragma unroll
            for (int j = 0; j < 2; j++) {
                uint32_t aPh[4] = { phA[2*j], phB[2*j], phA[2*j+1], phB[2*j+1] };
                #pragma unroll
                for (int dg = 0; dg < 8; dg++) {
                    uint32_t vaddr = (j * 16 + (lane & 15)) * FB_STRIDE_B
                                   + dg * 32 + (lane >> 4) * 16;
                    uint32_t fVh[4];
                    ldsm4t(fVh, sVh + vaddr);
                    mma_f16(accO[dg * 2],     aPh, fVh[0], fVh[1]);
                    mma_f16(accO[dg * 2 + 1], aPh, fVh[2], fVh[3]);
                }
            }
        }
        __syncthreads();
    }

    const float inv0 = 1.0f / l0, inv1 = 1.0f / l1;
    const size_t row0 = (size_t)(b * S_LEN + q0 + wid * 16 + (lane >> 2));
    const size_t row1 = row0 + 8;
    __half* oh0 = Oh_g + row0 * DIMN + h * HD;
    __half* oh1 = Oh_g + row1 * DIMN + h * HD;
    #pragma unroll
    for (int ti = 0; ti < 16; ti++) {
        int c = ti * 8 + (lane & 3) * 2;
        *(uint32_t*)(oh0 + c) = pack_h2(accO[ti][0] * inv0, accO[ti][1] * inv0);
        *(uint32_t*)(oh1 + c) = pack_h2(accO[ti][2] * inv1, accO[ti][3] * inv1);
    }
}

// ---------------------------------------------------------------------------
// Launch
// ---------------------------------------------------------------------------
extern "C" void kernel_launch(void* const* d_in, const int* in_sizes, int n_in,
                              void* d_out, int out_size)
{
    const float* x  = (const float*)d_in[0];
    const float* wq = (const float*)d_in[1];
    const float* wk = (const float*)d_in[2];
    const float* wv = (const float*)d_in[3];
    const float* wo = (const float*)d_in[4];
    float* out = (float*)d_out;

    __half *xh, *xl, *qh, *kh, *kl, *vh, *ah;
    __half *wqT, *wkT, *wvT, *woT;
    cudaGetSymbolAddress((void**)&xh, g_xh);   cudaGetSymbolAddress((void**)&xl, g_xl);
    cudaGetSymbolAddress((void**)&qh, g_qh);
    cudaGetSymbolAddress((void**)&kh, g_kh);   cudaGetSymbolAddress((void**)&kl, g_kl);
    cudaGetSymbolAddress((void**)&vh, g_vh);
    cudaGetSymbolAddress((void**)&ah, g_ah);
    cudaGetSymbolAddress((void**)&wqT, g_wqT); cudaGetSymbolAddress((void**)&wkT, g_wkT);
    cudaGetSymbolAddress((void**)&wvT, g_wvT); cudaGetSymbolAddress((void**)&woT, g_woT);

    cudaFuncSetAttribute(gemm_qkv,
                         cudaFuncAttributeMaxDynamicSharedMemorySize, QKV_SMEM);
    cudaFuncSetAttribute(gemm_wo,
                         cudaFuncAttributeMaxDynamicSharedMemorySize, WO_SMEM);
    cudaFuncSetAttribute(fattn_kernel,
                         cudaFuncAttributeMaxDynamicSharedMemorySize, FATTN_SMEM);

    conv_all<<<8192 + 320 * 128, 256>>>(
        x, xh, xl, wq, wk, wv, wo, wqT, wkT, wvT, woT);

    gemm_qkv<<<NSM_CTAS, 256, QKV_SMEM>>>(
        xh, xl, wqT, wkT, wvT, qh, kh, kl, vh);

    fattn_kernel<<<dim3(S_LEN / 128, HQ, BATCH), 256, FATTN_SMEM>>>(
        qh, kh, kl, vh, ah);

    gemm_wo<<<NSM_CTAS, 256, WO_SMEM>>>(
        MROWS, DIMN, DIMN, ah, woT, out);
}

// round 17
// speedup vs baseline: 1.0423x; 1.0197x over previous
#include <cuda_runtime.h>
#include <cuda_fp16.h>
#include <cstdint>

// Problem constants
#define DIMN    4096
#define S_LEN   2048
#define BATCH   2
#define HQ      32
#define HKV     8
#define NREP    4
#define HD      128
#define MROWS   (BATCH * S_LEN)   // 4096
#define KVDIM   (HKV * HD)        // 1024
#define NSM_CTAS 296              // 148 SMs x 2 CTAs

// ---------------------------------------------------------------------------
// Scratch (__device__ globals)
// ---------------------------------------------------------------------------
__device__ __half g_xh[(size_t)MROWS * DIMN];
__device__ __half g_xl[(size_t)MROWS * DIMN];
__device__ __half g_qh[(size_t)MROWS * DIMN];
__device__ __half g_kh[(size_t)MROWS * KVDIM];
__device__ __half g_kl[(size_t)MROWS * KVDIM];
__device__ __half g_vh[(size_t)MROWS * KVDIM];
__device__ __half g_ah[(size_t)MROWS * DIMN];
__device__ __half g_wqT[(size_t)DIMN * DIMN];
__device__ __half g_woT[(size_t)DIMN * DIMN];
__device__ __half g_wkT[(size_t)KVDIM * DIMN];
__device__ __half g_wvT[(size_t)KVDIM * DIMN];

// ---------------------------------------------------------------------------
// PTX helpers
// ---------------------------------------------------------------------------
__device__ __forceinline__ uint32_t smem_u32(const void* p) {
    return (uint32_t)__cvta_generic_to_shared(p);
}
__device__ __forceinline__ void ldsm4(uint32_t* r, uint32_t addr) {
    asm volatile("ldmatrix.sync.aligned.m8n8.x4.shared.b16 {%0,%1,%2,%3}, [%4];"
                 : "=r"(r[0]), "=r"(r[1]), "=r"(r[2]), "=r"(r[3]) : "r"(addr));
}
__device__ __forceinline__ void ldsm4t(uint32_t* r, uint32_t addr) {
    asm volatile("ldmatrix.sync.aligned.m8n8.x4.trans.shared.b16 {%0,%1,%2,%3}, [%4];"
                 : "=r"(r[0]), "=r"(r[1]), "=r"(r[2]), "=r"(r[3]) : "r"(addr));
}
__device__ __forceinline__ void mma_f16(float* d, const uint32_t* a,
                                        const uint32_t b0, const uint32_t b1) {
    asm volatile(
        "mma.sync.aligned.m16n8k16.row.col.f32.f16.f16.f32 "
        "{%0,%1,%2,%3}, {%4,%5,%6,%7}, {%8,%9}, {%0,%1,%2,%3};"
        : "+f"(d[0]), "+f"(d[1]), "+f"(d[2]), "+f"(d[3])
        : "r"(a[0]), "r"(a[1]), "r"(a[2]), "r"(a[3]), "r"(b0), "r"(b1));
}
__device__ __forceinline__ uint32_t pack_h2(float a, float b) {
    __half2 t = __floats2half2_rn(a, b);
    return *(uint32_t*)&t;
}
__device__ __forceinline__ float h_res(float v) {
    return v - __half2float(__float2half_rn(v));
}

// ---------------------------------------------------------------------------
// GEMM common: K-chunk 64, 2-stage pipeline.
// ---------------------------------------------------------------------------
constexpr int CK     = 64;
constexpr int PADW   = 72;
constexpr int PLANE  = 128 * PADW * 2;        // 18432 B
constexpr int GNS    = 2;
constexpr int QKV_SMEM = GNS * 3 * PLANE;     // 110592
constexpr int WO_SMEM  = GNS * 2 * PLANE;     // 73728

__device__ __forceinline__ void prefetch_rt(
    const __half* Ah, const __half* Al, const __half* Bh, int nterms,
    int K, int mtile, int ntile, int k0, uint32_t tbase, int tid)
{
    const int tot = (nterms + 1) * 1024;
    for (int u = tid; u < tot; u += 256) {
        int plane = u >> 10;
        int r = (u >> 3) & 127;
        int seg = u & 7;
        const __half* src;
        if (plane == 0)                     src = Ah + (size_t)(mtile + r) * K + k0 + seg * 8;
        else if (nterms == 2 && plane == 1) src = Al + (size_t)(mtile + r) * K + k0 + seg * 8;
        else                                src = Bh + (size_t)(ntile + r) * K + k0 + seg * 8;
        uint32_t dst = tbase + plane * PLANE + r * (PADW * 2) + seg * 16;
        asm volatile("cp.async.cg.shared.global [%0], [%1], 16;"
                     :: "r"(dst), "l"(src) : "memory");
    }
}

// ---------------------------------------------------------------------------
// Persistent merged Q|K|V projection GEMM (R16 form — measured win).
// 1536 tiles over NSM_CTAS CTAs.
// ---------------------------------------------------------------------------
__global__ __launch_bounds__(256, 2) void gemm_qkv(
    const __half* __restrict__ xh, const __half* __restrict__ xl,
    const __half* __restrict__ wqT, const __half* __restrict__ wkT,
    const __half* __restrict__ wvT,
    __half* __restrict__ qh, __half* __restrict__ kh,
    __half* __restrict__ kl, __half* __restrict__ vh)
{
    extern __shared__ char smem[];
    const uint32_t sbase = smem_u32(smem);

    const int tid = threadIdx.x;
    const int wid = tid >> 5, lane = tid & 31;
    const int wm = wid >> 2;
    const int wn = wid & 3;
    const int K = DIMN;
    const int nch = K / CK;

    const int a_row_in16 = (lane & 7) + ((lane >> 3) & 1) * 8;
    const int a_colb     = (lane >> 4) * 16;
    const int b_row_in16 = (lane & 7) + ((lane >> 4) & 1) * 8;
    const int b_colb     = ((lane >> 3) & 1) * 16;

    for (int tix = blockIdx.x; tix < 48 * (MROWS / 128); tix += gridDim.x) {
        const int nx = tix % 48;
        const int mtile = (tix / 48) * 128;

        const __half* B;
        __half *Oh, *Ol;
        int ntile, Nout, nterms;
        if (nx < 32)      { B = wqT; Oh = qh; Ol = nullptr; ntile = nx * 128;        Nout = DIMN;  nterms = 1; }
        else if (nx < 40) { B = wkT; Oh = kh; Ol = kl;      ntile = (nx - 32) * 128; Nout = KVDIM; nterms = 2; }
        else              { B = wvT; Oh = vh; Ol = nullptr; ntile = (nx - 40) * 128; Nout = KVDIM; nterms = 1; }
        const int STG = (nterms + 1) * PLANE;

        float acc[4][4][4];
        #pragma unroll
        for (int mi = 0; mi < 4; mi++)
            #pragma unroll
            for (int ni = 0; ni < 4; ni++)
                #pragma unroll
                for (int e = 0; e < 4; e++) acc[mi][ni][e] = 0.f;

        for (int i = 0; i < GNS; i++) {
            prefetch_rt(xh, xl, B, nterms, K, mtile, ntile, i * CK, sbase + i * STG, tid);
            asm volatile("cp.async.commit_group;" ::: "memory");
        }

        for (int i = 0; i < nch; i++) {
            const int s = i % GNS;
            const uint32_t tb = sbase + s * STG;
            asm volatile("cp.async.wait_group %0;" :: "n"(GNS - 1) : "memory");
            __syncthreads();

            const uint32_t aH = tb;
            const uint32_t aL = tb + PLANE;
            const uint32_t bH = tb + nterms * PLANE;

            #pragma unroll
            for (int ks = 0; ks < 4; ks++) {
                const int kb = ks * 32;
                uint32_t fB[2][4];
                #pragma unroll
                for (int ng = 0; ng < 2; ng++) {
                    int row = wn * 32 + ng * 16 + b_row_in16;
                    ldsm4(fB[ng], bH + row * (PADW * 2) + b_colb + kb);
                }
                uint32_t fA[4][4];
                #pragma unroll
                for (int mi = 0; mi < 4; mi++) {
                    int row = wm * 64 + mi * 16 + a_row_in16;
                    ldsm4(fA[mi], aH + row * (PADW * 2) + a_colb + kb);
                }
                #pragma unroll
                for (int mi = 0; mi < 4; mi++)
                    #pragma unroll
                    for (int ni = 0; ni < 4; ni++) {
                        const int ng = ni >> 1, hf = (ni & 1) * 2;
                        mma_f16(acc[mi][ni], fA[mi], fB[ng][hf], fB[ng][hf + 1]);
                    }
                if (nterms == 2) {
                    #pragma unroll
                    for (int mi = 0; mi < 4; mi++) {
                        int row = wm * 64 + mi * 16 + a_row_in16;
                        ldsm4(fA[mi], aL + row * (PADW * 2) + a_colb + kb);
                    }
                    #pragma unroll
                    for (int mi = 0; mi < 4; mi++)
                        #pragma unroll
                        for (int ni = 0; ni < 4; ni++) {
                            const int ng = ni >> 1, hf = (ni & 1) * 2;
                            mma_f16(acc[mi][ni], fA[mi], fB[ng][hf], fB[ng][hf + 1]);
                        }
                }
            }
            __syncthreads();

            if (i + GNS < nch)
                prefetch_rt(xh, xl, B, nterms, K, mtile, ntile, (i + GNS) * CK,
                            sbase + s * STG, tid);
            asm volatile("cp.async.commit_group;" ::: "memory");
        }

        const int r0b = mtile + wm * 64 + (lane >> 2);
        const int c0b = ntile + wn * 32 + (lane & 3) * 2;
        #pragma unroll
        for (int mi = 0; mi < 4; mi++) {
            #pragma unroll
            for (int ni = 0; ni < 4; ni++) {
                size_t o0 = (size_t)(r0b + mi * 16) * Nout + c0b + ni * 8;
                size_t o1 = (size_t)(r0b + mi * 16 + 8) * Nout + c0b + ni * 8;
                float v0 = acc[mi][ni][0], v1 = acc[mi][ni][1];
                float v2 = acc[mi][ni][2], v3 = acc[mi][ni][3];
                *(uint32_t*)(Oh + o0) = pack_h2(v0, v1);
                *(uint32_t*)(Oh + o1) = pack_h2(v2, v3);
                if (Ol != nullptr) {
                    *(uint32_t*)(Ol + o0) = pack_h2(h_res(v0), h_res(v1));
                    *(uint32_t*)(Ol + o1) = pack_h2(h_res(v2), h_res(v3));
                }
            }
        }
    }
}

// ---------------------------------------------------------------------------
// wo GEMM: gridded launch (R15 form — measured 368 us). 1-term, fp32 out.
// ---------------------------------------------------------------------------
__global__ __launch_bounds__(256, 2) void gemm_wo(
    int M, int N, int K,
    const __half* __restrict__ Ah, const __half* __restrict__ Bh,
    float* __restrict__ C)
{
    constexpr int STG = 2 * PLANE;
    extern __shared__ char smem[];
    const uint32_t sbase = smem_u32(smem);

    const int tid = threadIdx.x;
    const int wid = tid >> 5, lane = tid & 31;
    const int wm = wid >> 2;
    const int wn = wid & 3;
    const int mtile = blockIdx.y * 128;
    const int ntile = blockIdx.x * 128;
    const int nch = K / CK;

    float acc[4][4][4];
    #pragma unroll
    for (int mi = 0; mi < 4; mi++)
        #pragma unroll
        for (int ni = 0; ni < 4; ni++)
            #pragma unroll
            for (int e = 0; e < 4; e++) acc[mi][ni][e] = 0.f;

    const int a_row_in16 = (lane & 7) + ((lane >> 3) & 1) * 8;
    const int a_colb     = (lane >> 4) * 16;
    const int b_row_in16 = (lane & 7) + ((lane >> 4) & 1) * 8;
    const int b_colb     = ((lane >> 3) & 1) * 16;

    for (int i = 0; i < GNS; i++) {
        prefetch_rt(Ah, nullptr, Bh, 1, K, mtile, ntile, i * CK, sbase + i * STG, tid);
        asm volatile("cp.async.commit_group;" ::: "memory");
    }

    for (int i = 0; i < nch; i++) {
        const int s = i % GNS;
        const uint32_t tb = sbase + s * STG;
        asm volatile("cp.async.wait_group %0;" :: "n"(GNS - 1) : "memory");
        __syncthreads();

        const uint32_t aH = tb;
        const uint32_t bH = tb + PLANE;

        #pragma unroll
        for (int ks = 0; ks < 4; ks++) {
            const int kb = ks * 32;
            uint32_t fB[2][4];
            #pragma unroll
            for (int ng = 0; ng < 2; ng++) {
                int row = wn * 32 + ng * 16 + b_row_in16;
                ldsm4(fB[ng], bH + row * (PADW * 2) + b_colb + kb);
            }
            uint32_t fA[4][4];
            #pragma unroll
            for (int mi = 0; mi < 4; mi++) {
                int row = wm * 64 + mi * 16 + a_row_in16;
                ldsm4(fA[mi], aH + row * (PADW * 2) + a_colb + kb);
            }
            #pragma unroll
            for (int mi = 0; mi < 4; mi++)
                #pragma unroll
                for (int ni = 0; ni < 4; ni++) {
                    const int ng = ni >> 1, hf = (ni & 1) * 2;
                    mma_f16(acc[mi][ni], fA[mi], fB[ng][hf], fB[ng][hf + 1]);
                }
        }
        __syncthreads();

        if (i + GNS < nch)
            prefetch_rt(Ah, nullptr, Bh, 1, K, mtile, ntile, (i + GNS) * CK,
                        sbase + s * STG, tid);
        asm volatile("cp.async.commit_group;" ::: "memory");
    }

    const int r0b = mtile + wm * 64 + (lane >> 2);
    const int c0b = ntile + wn * 32 + (lane & 3) * 2;
    #pragma unroll
    for (int mi = 0; mi < 4; mi++) {
        #pragma unroll
        for (int ni = 0; ni < 4; ni++) {
            size_t o0 = (size_t)(r0b + mi * 16) * N + c0b + ni * 8;
            size_t o1 = (size_t)(r0b + mi * 16 + 8) * N + c0b + ni * 8;
            *(float2*)(C + o0) = make_float2(acc[mi][ni][0], acc[mi][ni][1]);
            *(float2*)(C + o1) = make_float2(acc[mi][ni][2], acc[mi][ni][3]);
        }
    }
}

// ---------------------------------------------------------------------------
// Merged conversion kernel (R15 form).
// ---------------------------------------------------------------------------
__global__ void conv_all(
    const float* __restrict__ x,
    __half* __restrict__ xh, __half* __restrict__ xl,
    const float* __restrict__ wq, const float* __restrict__ wk,
    const float* __restrict__ wv, const float* __restrict__ wo,
    __half* __restrict__ wqT, __half* __restrict__ wkT,
    __half* __restrict__ wvT, __half* __restrict__ woT)
{
    const int gx = blockIdx.x;
    const int tid = threadIdx.x;
    if (gx < 8192) {
        int i = gx * 256 + tid;
        float4 v0 = ((const float4*)x)[2 * i];
        float4 v1 = ((const float4*)x)[2 * i + 1];
        uint4 h, l;
        h.x = pack_h2(v0.x, v0.y);  h.y = pack_h2(v0.z, v0.w);
        h.z = pack_h2(v1.x, v1.y);  h.w = pack_h2(v1.z, v1.w);
        l.x = pack_h2(h_res(v0.x), h_res(v0.y));
        l.y = pack_h2(h_res(v0.z), h_res(v0.w));
        l.z = pack_h2(h_res(v1.x), h_res(v1.y));
        l.w = pack_h2(h_res(v1.z), h_res(v1.w));
        ((uint4*)xh)[i] = h;
        ((uint4*)xl)[i] = l;
        return;
    }
    __shared__ float t[32][33];
    const int tt = gx - 8192;
    const int ky = tt / 320;
    const int kx = tt - ky * 320;
    const float* W;
    __half* Th;
    int n0, N;
    if (kx < 128)      { W = wq; Th = wqT; n0 = kx * 32;         N = DIMN; }
    else if (kx < 160) { W = wk; Th = wkT; n0 = (kx - 128) * 32; N = KVDIM; }
    else if (kx < 192) { W = wv; Th = wvT; n0 = (kx - 160) * 32; N = KVDIM; }
    else               { W = wo; Th = woT; n0 = (kx - 192) * 32; N = DIMN; }
    const int K = DIMN;
    const int k0 = ky * 32;
    const int tx = tid & 31, ty0 = tid >> 5;
    #pragma unroll
    for (int j = 0; j < 4; j++) {
        int ty = ty0 + 8 * j;
        t[ty][tx] = W[(size_t)(k0 + ty) * N + n0 + tx];
    }
    __syncthreads();
    #pragma unroll
    for (int j = 0; j < 4; j++) {
        int ty = ty0 + 8 * j;
        Th[(size_t)(n0 + ty) * K + k0 + tx] = __float2half_rn(t[tx][ty]);
    }
}

// ---------------------------------------------------------------------------
// fp16 flash attention (R15 form, unchanged).
// ---------------------------------------------------------------------------
constexpr int FB_STRIDE_B = 272;
constexpr int KT = 32;
constexpr int FPLANE  = KT * FB_STRIDE_B;       // 8704
constexpr int QPLANE  = 128 * FB_STRIDE_B;      // 34816
constexpr int FATTN_SMEM = QPLANE + 9 * FPLANE;  // 113152

__global__ __launch_bounds__(256, 2) void fattn_kernel(
    const __half* __restrict__ Qh_g,
    const __half* __restrict__ Kh_g, const __half* __restrict__ Kl_g,
    const __half* __restrict__ Vh_g,
    __half* __restrict__ Oh_g)
{
    extern __shared__ char smem[];
    const uint32_t sb = smem_u32(smem);
    const uint32_t sQh = sb;
    const uint32_t kvstart = sb + QPLANE;

    const int tid = threadIdx.x, wid = tid >> 5, lane = tid & 31;
    const int bx = gridDim.x - 1 - blockIdx.x;
    const int h = blockIdx.y, b = blockIdx.z;
    const int q0 = bx * 128;
    const int kvh = h >> 2;

    const __half* qh = Qh_g + ((size_t)(b * S_LEN + q0)) * DIMN + h * HD;
    const __half* kh = Kh_g + ((size_t)(b * S_LEN)) * KVDIM + kvh * HD;
    const __half* kl = Kl_g + ((size_t)(b * S_LEN)) * KVDIM + kvh * HD;
    const __half* vh = Vh_g + ((size_t)(b * S_LEN)) * KVDIM + kvh * HD;

    auto load_kv = [&](int kt0, int s) {
        const uint32_t base = kvstart + 3 * s * FPLANE;
        #pragma unroll
        for (int u = tid; u < 1536; u += 256) {
            int plane = u / 512, r = (u >> 4) & 31, seg = u & 15;
            const __half* src;
            if (plane == 0)      src = kh;
            else if (plane == 1) src = kl;
            else                 src = vh;
            src += (size_t)(kt0 + r) * KVDIM + seg * 8;
            uint32_t dst = base + plane * FPLANE + r * FB_STRIDE_B + seg * 16;
            asm volatile("cp.async.cg.shared.global [%0], [%1], 16;"
                         :: "r"(dst), "l"(src) : "memory");
        }
    };

    #pragma unroll
    for (int u = tid; u < 2048; u += 256) {
        int r = (u >> 4) & 127, seg = u & 15;
        const __half* src = qh + (size_t)r * DIMN + seg * 8;
        uint32_t dst = sQh + r * FB_STRIDE_B + seg * 16;
        asm volatile("cp.async.cg.shared.global [%0], [%1], 16;"
                     :: "r"(dst), "l"(src) : "memory");
    }
    load_kv(0, 0);
    asm volatile("cp.async.commit_group;" ::: "memory");
    load_kv(KT, 1);
    asm volatile("cp.async.commit_group;" ::: "memory");

    float accO[16][4];
    #pragma unroll
    for (int t = 0; t < 16; t++)
        #pragma unroll
        for (int e = 0; e < 4; e++) accO[t][e] = 0.f;
    float m0 = -1e30f, m1 = -1e30f, l0 = 0.f, l1 = 0.f;

    const int a_r  = (lane & 7) + ((lane >> 3) & 1) * 8;
    const int a_cb = (lane >> 4) * 16;
    const int b_r  = (lane & 7) + ((lane >> 4) & 1) * 8;
    const int b_cb = ((lane >> 3) & 1) * 16;

    const float SL = 0.08838834764831845f * 1.4426950408889634f;

    const int n_tiles = 4 * bx + 4;
    for (int t = 0; t < n_tiles; t++) {
        const int kt0 = t * KT;
        const int cur = t % 3;
        if (t + 2 < n_tiles) load_kv((t + 2) * KT, (t + 2) % 3);
        asm volatile("cp.async.commit_group;" ::: "memory");
        asm volatile("cp.async.wait_group %0;" :: "n"(2) : "memory");
        __syncthreads();

        const bool active = (kt0 <= q0 + wid * 16 + 15);

        if (active) {
            const uint32_t kvb = kvstart + 3 * cur * FPLANE;
            const uint32_t sKh = kvb, sKl = kvb + FPLANE, sVh = kvb + 2 * FPLANE;

            float accS[4][4];
            #pragma unroll
            for (int ni = 0; ni < 4; ni++)
                #pragma unroll
                for (int e = 0; e < 4; e++) accS[ni][e] = 0.f;

            #pragma unroll
            for (int kk = 0; kk < 8; kk++) {
                uint32_t fQ[4];
                uint32_t aaddr = (wid * 16 + a_r) * FB_STRIDE_B + kk * 32 + a_cb;
                ldsm4(fQ, sQh + aaddr);
                #pragma unroll
                for (int ng = 0; ng < 2; ng++) {
                    uint32_t baddr = (ng * 16 + b_r) * FB_STRIDE_B + kk * 32 + b_cb;
                    uint32_t fKh[4], fKl[4];
                    ldsm4(fKh, sKh + baddr);
                    ldsm4(fKl, sKl + baddr);
                    #pragma unroll
                    for (int hf2 = 0; hf2 < 2; hf2++) {
                        const int ni = ng * 2 + hf2;
                        mma_f16(accS[ni], fQ, fKh[hf2 * 2], fKh[hf2 * 2 + 1]);
                        mma_f16(accS[ni], fQ, fKl[hf2 * 2], fKl[hf2 * 2 + 1]);
                    }
                }
            }

            if (t >= n_tiles - 4) {
                const int r0 = q0 + wid * 16 + (lane >> 2);
                #pragma unroll
                for (int ni = 0; ni < 4; ni++) {
                    int c = kt0 + ni * 8 + (lane & 3) * 2;
                    if (c > r0)     accS[ni][0] = -1e30f;
                    if (c + 1 > r0) accS[ni][1] = -1e30f;
                    if (c > r0 + 8)     accS[ni][2] = -1e30f;
                    if (c + 1 > r0 + 8) accS[ni][3] = -1e30f;
                }
            }

            float mx0 = -1e30f, mx1 = -1e30f;
            #pragma unroll
            for (int ni = 0; ni < 4; ni++) {
                mx0 = fmaxf(mx0, fmaxf(accS[ni][0], accS[ni][1]));
                mx1 = fmaxf(mx1, fmaxf(accS[ni][2], accS[ni][3]));
            }
            mx0 = fmaxf(mx0, __shfl_xor_sync(0xffffffffu, mx0, 1));
            mx0 = fmaxf(mx0, __shfl_xor_sync(0xffffffffu, mx0, 2));
            mx1 = fmaxf(mx1, __shfl_xor_sync(0xffffffffu, mx1, 1));
            mx1 = fmaxf(mx1, __shfl_xor_sync(0xffffffffu, mx1, 2));

            const float mn0 = fmaxf(m0, mx0), mn1 = fmaxf(m1, mx1);
            const float al0 = exp2f((m0 - mn0) * SL);
            const float al1 = exp2f((m1 - mn1) * SL);
            m0 = mn0; m1 = mn1;
            const float nm0 = -mn0 * SL, nm1 = -mn1 * SL;

            uint32_t phA[4], phB[4];
            float s0 = 0.f, s1 = 0.f;
            #pragma unroll
            for (int ni = 0; ni < 4; ni++) {
                float p0 = exp2f(fmaf(accS[ni][0], SL, nm0));
                float p1 = exp2f(fmaf(accS[ni][1], SL, nm0));
                float p2 = exp2f(fmaf(accS[ni][2], SL, nm1));
                float p3 = exp2f(fmaf(accS[ni][3], SL, nm1));
                s0 += p0 + p1; s1 += p2 + p3;
                phA[ni] = pack_h2(p0, p1);
                phB[ni] = pack_h2(p2, p3);
            }
            s0 += __shfl_xor_sync(0xffffffffu, s0, 1);
            s0 += __shfl_xor_sync(0xffffffffu, s0, 2);
            s1 += __shfl_xor_sync(0xffffffffu, s1, 1);
            s1 += __shfl_xor_sync(0xffffffffu, s1, 2);
            l0 = l0 * al0 + s0;
            l1 = l1 * al1 + s1;

            #pragma unroll
            for (int ti = 0; ti < 16; ti++) {
                accO[ti][0] *= al0; accO[ti][1] *= al0;
                accO[ti][2] *= al1; accO[ti][3] *= al1;
            }

            #pragma unroll
            for (int j = 0; j < 2; j++) {
                uint32_t aPh[4] = { phA[2*j], phB[2*j], phA[2*j+1], phB[2*j+1] };
                #pragma unroll
                for (int dg = 0; dg < 8; dg++) {
                    uint32_t vaddr = (j * 16 + (lane & 15)) * FB_STRIDE_B
                                   + dg * 32 + (lane >> 4) * 16;
                    uint32_t fVh[4];
                    ldsm4t(fVh, sVh + vaddr);
                    mma_f16(accO[dg * 2],     aPh, fVh[0], fVh[1]);
                    mma_f16(accO[dg * 2 + 1], aPh, fVh[2], fVh[3]);
                }
            }
        }
        __syncthreads();
    }

    const float inv0 = 1.0f / l0, inv1 = 1.0f / l1;
    const size_t row0 = (size_t)(b * S_LEN + q0 + wid * 16 + (lane >> 2));
    const size_t row1 = row0 + 8;
    __half* oh0 = Oh_g + row0 * DIMN + h * HD;
    __half* oh1 = Oh_g + row1 * DIMN + h * HD;
    #pragma unroll
    for (int ti = 0; ti < 16; ti++) {
        int c = ti * 8 + (lane & 3) * 2;
        *(uint32_t*)(oh0 + c) = pack_h2(accO[ti][0] * inv0, accO[ti][1] * inv0);
        *(uint32_t*)(oh1 + c) = pack_h2(accO[ti][2] * inv1, accO[ti][3] * inv1);
    }
}

// ---------------------------------------------------------------------------
// Launch
// ---------------------------------------------------------------------------
extern "C" void kernel_launch(void* const* d_in, const int* in_sizes, int n_in,
                              void* d_out, int out_size)
{
    const float* x  = (const float*)d_in[0];
    const float* wq = (const float*)d_in[1];
    const float* wk = (const float*)d_in[2];
    const float* wv = (const float*)d_in[3];
    const float* wo = (const float*)d_in[4];
    float* out = (float*)d_out;

    __half *xh, *xl, *qh, *kh, *kl, *vh, *ah;
    __half *wqT, *wkT, *wvT, *woT;
    cudaGetSymbolAddress((void**)&xh, g_xh);   cudaGetSymbolAddress((void**)&xl, g_xl);
    cudaGetSymbolAddress((void**)&qh, g_qh);
    cudaGetSymbolAddress((void**)&kh, g_kh);   cudaGetSymbolAddress((void**)&kl, g_kl);
    cudaGetSymbolAddress((void**)&vh, g_vh);
    cudaGetSymbolAddress((void**)&ah, g_ah);
    cudaGetSymbolAddress((void**)&wqT, g_wqT); cudaGetSymbolAddress((void**)&wkT, g_wkT);
    cudaGetSymbolAddress((void**)&wvT, g_wvT); cudaGetSymbolAddress((void**)&woT, g_woT);

    cudaFuncSetAttribute(gemm_qkv,
                         cudaFuncAttributeMaxDynamicSharedMemorySize, QKV_SMEM);
    cudaFuncSetAttribute(gemm_wo,
                         cudaFuncAttributeMaxDynamicSharedMemorySize, WO_SMEM);
    cudaFuncSetAttribute(fattn_kernel,
                         cudaFuncAttributeMaxDynamicSharedMemorySize, FATTN_SMEM);

    conv_all<<<8192 + 320 * 128, 256>>>(
        x, xh, xl, wq, wk, wv, wo, wqT, wkT, wvT, woT);

    gemm_qkv<<<NSM_CTAS, 256, QKV_SMEM>>>(
        xh, xl, wqT, wkT, wvT, qh, kh, kl, vh);

    fattn_kernel<<<dim3(S_LEN / 128, HQ, BATCH), 256, FATTN_SMEM>>>(
        qh, kh, kl, vh, ah);

    gemm_wo<<<dim3(DIMN / 128, MROWS / 128), 256, WO_SMEM>>>(
        MROWS, DIMN, DIMN, ah, woT, out);
}